// round 1
// baseline (speedup 1.0000x reference)
#include <cuda_runtime.h>
#include <math.h>

// ---------------- problem constants ----------------
#define B_   8
#define S_   512
#define P_   8
#define F_   512
#define D_   4096      // P_*F_
#define O_   512
#define C_   1536      // 3*O_
#define MROWS 32768    // B_*S_*P_
static const long long HHALF = 50331648ll;   // MROWS * C_

// ---------------- GEMM tiling ----------------
#define BK 8
#define BM 128
#define BN 128

// ---------------- scratch (__device__ globals; no allocation allowed) ------
__device__ float g_nb1[16777216];   // B*S*D
__device__ float g_nb2[16777216];
__device__ float g_mu1[16777216];
__device__ float g_mu2[16777216];
__device__ float g_sim [2097152];   // B*S*S
__device__ float g_att1[2097152];
__device__ float g_att2[2097152];   // stored [b][j][i]
__device__ float g_n1[4096];        // B*S
__device__ float g_n2[4096];
__device__ float g_sums [3072];     // 2*C
__device__ float g_sumsq[3072];
__device__ float g_scalev[3072];
__device__ float g_shiftv[3072];

// ---------------- reduction helpers (256-thread blocks) ----------------
__device__ __forceinline__ float block_sum(float v) {
    __shared__ float red[8];
    #pragma unroll
    for (int o = 16; o; o >>= 1) v += __shfl_xor_sync(0xffffffffu, v, o);
    if ((threadIdx.x & 31) == 0) red[threadIdx.x >> 5] = v;
    __syncthreads();
    v = red[threadIdx.x & 7];
    #pragma unroll
    for (int o = 4; o; o >>= 1) v += __shfl_xor_sync(0xffffffffu, v, o);
    return v;
}

__device__ __forceinline__ float block_max(float v) {
    __shared__ float redm[8];
    #pragma unroll
    for (int o = 16; o; o >>= 1) v = fmaxf(v, __shfl_xor_sync(0xffffffffu, v, o));
    if ((threadIdx.x & 31) == 0) redm[threadIdx.x >> 5] = v;
    __syncthreads();
    v = redm[threadIdx.x & 7];
    #pragma unroll
    for (int o = 4; o; o >>= 1) v = fmaxf(v, __shfl_xor_sync(0xffffffffu, v, o));
    return v;
}

// ---------------- GEMM mainloops ----------------
// NT: C[m,n] = sum_k A[m*lda+k] * B[n*ldb+k]   (both K-contiguous)
// Caller pre-offsets A by m0*lda and B by n0*ldb.
__device__ __forceinline__ void gemm_nt(const float* __restrict__ A,
                                        const float* __restrict__ Bm,
                                        int K, int lda, int ldb,
                                        float acc[8][8]) {
    __shared__ __align__(16) float As[BK][BM + 4];
    __shared__ __align__(16) float Bs[BK][BM + 4];
    const int tid  = threadIdx.x;
    const int tx   = tid & 15, ty = tid >> 4;
    const int lrow = tid >> 1, lcol = (tid & 1) * 4;
    const float* Ap = A + (size_t)lrow * lda + lcol;
    const float* Bp = Bm + (size_t)lrow * ldb + lcol;
    for (int k0 = 0; k0 < K; k0 += BK) {
        float4 av = *(const float4*)(Ap + k0);
        float4 bv = *(const float4*)(Bp + k0);
        __syncthreads();
        As[lcol + 0][lrow] = av.x; As[lcol + 1][lrow] = av.y;
        As[lcol + 2][lrow] = av.z; As[lcol + 3][lrow] = av.w;
        Bs[lcol + 0][lrow] = bv.x; Bs[lcol + 1][lrow] = bv.y;
        Bs[lcol + 2][lrow] = bv.z; Bs[lcol + 3][lrow] = bv.w;
        __syncthreads();
        #pragma unroll
        for (int kk = 0; kk < BK; kk++) {
            float a[8], b[8];
            #pragma unroll
            for (int r = 0; r < 8; r++) a[r] = As[kk][ty * 8 + r];
            #pragma unroll
            for (int c = 0; c < 8; c++) b[c] = Bs[kk][tx * 8 + c];
            #pragma unroll
            for (int r = 0; r < 8; r++)
                #pragma unroll
                for (int c = 0; c < 8; c++) acc[r][c] += a[r] * b[c];
        }
    }
}

// NN: C[m,n] = sum_k A[m*lda+k] * B[k*ldb+n]   (A K-contig, B N-contig)
// Caller pre-offsets A by m0*lda and B by n0.
__device__ __forceinline__ void gemm_nn(const float* __restrict__ A,
                                        const float* __restrict__ Bm,
                                        int K, int lda, int ldb,
                                        float acc[8][8]) {
    __shared__ __align__(16) float As[BK][BM + 4];
    __shared__ __align__(16) float Bs[BK][BN + 4];
    const int tid  = threadIdx.x;
    const int tx   = tid & 15, ty = tid >> 4;
    const int arow = tid >> 1, acol = (tid & 1) * 4;
    const int brow = tid >> 5, bcol = (tid & 31) * 4;
    const float* Ap = A + (size_t)arow * lda + acol;
    const float* Bp = Bm + (size_t)brow * ldb + bcol;
    for (int k0 = 0; k0 < K; k0 += BK) {
        float4 av = *(const float4*)(Ap + k0);
        float4 bv = *(const float4*)(Bp + (size_t)k0 * ldb);
        __syncthreads();
        As[acol + 0][arow] = av.x; As[acol + 1][arow] = av.y;
        As[acol + 2][arow] = av.z; As[acol + 3][arow] = av.w;
        *(float4*)&Bs[brow][bcol] = bv;
        __syncthreads();
        #pragma unroll
        for (int kk = 0; kk < BK; kk++) {
            float a[8], b[8];
            #pragma unroll
            for (int r = 0; r < 8; r++) a[r] = As[kk][ty * 8 + r];
            #pragma unroll
            for (int c = 0; c < 8; c++) b[c] = Bs[kk][tx * 8 + c];
            #pragma unroll
            for (int r = 0; r < 8; r++)
                #pragma unroll
                for (int c = 0; c < 8; c++) acc[r][c] += a[r] * b[c];
        }
    }
}

// ---------------- kernels ----------------
__global__ void zero_stats_kernel() {
    int i = blockIdx.x * 256 + threadIdx.x;
    if (i < 2 * C_) { g_sums[i] = 0.0f; g_sumsq[i] = 0.0f; }
}

// ||x_f[b,i,:]|| over D=4096. grid = 2*B*S blocks.
__global__ void norms_kernel(const float* __restrict__ x1,
                             const float* __restrict__ x2) {
    int blk = blockIdx.x;
    int t = blk >> 12;
    int bi = blk & 4095;
    const float* x = (t ? x2 : x1) + (size_t)bi * D_;
    float s = 0.0f;
    for (int k = threadIdx.x; k < D_; k += 256) { float v = x[k]; s += v * v; }
    s = block_sum(s);
    if (threadIdx.x == 0) (t ? g_n2 : g_n1)[bi] = sqrtf(s);
}

// neighbor mean over adjacency (diag excluded). grid = 2*B*S blocks, 256 thr.
__global__ void neigh_kernel(const float* __restrict__ x1,
                             const float* __restrict__ x2,
                             const int* __restrict__ adj1,
                             const int* __restrict__ adj2) {
    int blk = blockIdx.x;
    int t  = blk >> 12;
    int bi = blk & 4095;
    int b = bi >> 9, i = bi & 511;
    const int* adj = (t ? adj2 : adj1) + (size_t)(b * S_ + i) * S_;
    const float* x = (t ? x2 : x1) + (size_t)b * S_ * D_;
    float* nb = (t ? g_nb2 : g_nb1) + (size_t)bi * D_;
    __shared__ int row[S_];
    for (int j = threadIdx.x; j < S_; j += 256) row[j] = adj[j];
    __syncthreads();
    float acc[16];
    #pragma unroll
    for (int k = 0; k < 16; k++) acc[k] = 0.0f;
    int deg = 0;
    for (int j = 0; j < S_; j++) {
        if (row[j] > 0 && j != i) {
            deg++;
            const float* xr = x + (size_t)j * D_ + threadIdx.x;
            #pragma unroll
            for (int k = 0; k < 16; k++) acc[k] += xr[k * 256];
        }
    }
    float inv = 1.0f / (float)deg;
    #pragma unroll
    for (int k = 0; k < 16; k++) nb[threadIdx.x + k * 256] = acc[k] * inv;
}

// sim[b,i,j] = <x1f[b,i], x2f[b,j]> / max(n1*n2, 1e-6).  grid (4,4,8).
__global__ __launch_bounds__(256) void sim_gemm_kernel(const float* __restrict__ x1,
                                                       const float* __restrict__ x2) {
    int b = blockIdx.z;
    int m0 = blockIdx.y * BM, n0 = blockIdx.x * BN;
    const float* A  = x1 + (size_t)b * S_ * D_ + (size_t)m0 * D_;
    const float* Bm = x2 + (size_t)b * S_ * D_ + (size_t)n0 * D_;
    float acc[8][8] = {};
    gemm_nt(A, Bm, D_, D_, D_, acc);
    const int tx = threadIdx.x & 15, ty = threadIdx.x >> 4;
    const float* n1 = g_n1 + b * S_;
    const float* n2 = g_n2 + b * S_;
    float* C = g_sim + (size_t)b * S_ * S_;
    #pragma unroll
    for (int r = 0; r < 8; r++) {
        int m = m0 + ty * 8 + r;
        float nm = n1[m];
        float* crow = C + (size_t)m * S_ + n0 + tx * 8;
        #pragma unroll
        for (int c = 0; c < 8; c++)
            crow[c] = acc[r][c] / fmaxf(nm * n2[n0 + tx * 8 + c], 1e-6f);
    }
}

// att1[b,i,:] = softmax_j sim[b,i,j].  grid = B*S.
__global__ void softmax_row_kernel() {
    int bi = blockIdx.x;
    const float* srow = g_sim + (size_t)bi * S_;
    float* drow = g_att1 + (size_t)bi * S_;
    int tid = threadIdx.x;
    float v0 = srow[tid], v1 = srow[tid + 256];
    float mx = block_max(fmaxf(v0, v1));
    float e0 = expf(v0 - mx), e1 = expf(v1 - mx);
    float s = block_sum(e0 + e1);
    float inv = 1.0f / s;
    drow[tid] = e0 * inv;
    drow[tid + 256] = e1 * inv;
}

// att2[b,j,i] = softmax_i sim[b,i,j]  (column softmax, stored transposed).
__global__ void softmax_col_kernel() {
    int bi = blockIdx.x;           // b*S + j
    int b = bi >> 9, j = bi & 511;
    const float* base = g_sim + (size_t)b * S_ * S_ + j;
    float* drow = g_att2 + (size_t)bi * S_;
    int tid = threadIdx.x;
    float v0 = base[(size_t)tid * S_];
    float v1 = base[(size_t)(tid + 256) * S_];
    float mx = block_max(fmaxf(v0, v1));
    float e0 = expf(v0 - mx), e1 = expf(v1 - mx);
    float s = block_sum(e0 + e1);
    float inv = 1.0f / s;
    drow[tid] = e0 * inv;
    drow[tid + 256] = e1 * inv;
}

// mu = x_self - att @ x_other.   grid (32,4,8).
__global__ __launch_bounds__(256) void mu_gemm_kernel(const float* __restrict__ x1,
                                                      const float* __restrict__ x2,
                                                      int t) {
    int b = blockIdx.z;
    const float* A    = (t ? g_att2 : g_att1) + (size_t)b * S_ * S_;
    const float* Bsrc = (t ? x1 : x2) + (size_t)b * S_ * D_;
    const float* Xs   = (t ? x2 : x1) + (size_t)b * S_ * D_;
    float* Cm         = (t ? g_mu2 : g_mu1) + (size_t)b * S_ * D_;
    int m0 = blockIdx.y * BM, n0 = blockIdx.x * BN;
    float acc[8][8] = {};
    gemm_nn(A + (size_t)m0 * S_, Bsrc + n0, S_, S_, D_, acc);
    const int tx = threadIdx.x & 15, ty = threadIdx.x >> 4;
    #pragma unroll
    for (int r = 0; r < 8; r++) {
        size_t m = m0 + ty * 8 + r;
        const float* xrow = Xs + m * (size_t)D_ + n0 + tx * 8;
        float* crow = Cm + m * (size_t)D_ + n0 + tx * 8;
        #pragma unroll
        for (int c = 0; c < 8; c++) crow[c] = xrow[c] - acc[r][c];
    }
}

// h segment: out[m*1536 + n] = A[m,:]·W[n,:] + bias[n].  grid (4, 256).
// out already offset by stream-half and segment*512.
__global__ __launch_bounds__(256) void lin_gemm_kernel(const float* __restrict__ x1,
                                                       const float* __restrict__ x2,
                                                       const float* __restrict__ W,
                                                       const float* __restrict__ bias,
                                                       float* __restrict__ out,
                                                       int sel) {
    const float* Abase =
        sel == 0 ? x1    : sel == 1 ? g_nb1 : sel == 2 ? g_mu1 :
        sel == 3 ? x2    : sel == 4 ? g_nb2 :             g_mu2;
    int m0 = blockIdx.y * BM, n0 = blockIdx.x * BN;
    float acc[8][8] = {};
    gemm_nt(Abase + (size_t)m0 * F_, W + (size_t)n0 * F_, F_, F_, F_, acc);
    const int tx = threadIdx.x & 15, ty = threadIdx.x >> 4;
    #pragma unroll
    for (int r = 0; r < 8; r++) {
        size_t m = m0 + ty * 8 + r;
        float* crow = out + m * (size_t)C_ + n0 + tx * 8;
        #pragma unroll
        for (int c = 0; c < 8; c++)
            crow[c] = acc[r][c] + bias[n0 + tx * 8 + c];
    }
}

// relu(h / max(||h||_row, 1e-12)) in place.  grid = 2*MROWS rows.
__global__ void normrelu_kernel(float* __restrict__ out) {
    size_t row = blockIdx.x;
    float* p = out + row * (size_t)C_;
    int tid = threadIdx.x;
    float v[6];
    float s = 0.0f;
    #pragma unroll
    for (int k = 0; k < 6; k++) { v[k] = p[tid + k * 256]; s += v[k] * v[k]; }
    s = block_sum(s);
    float inv = 1.0f / fmaxf(sqrtf(s), 1e-12f);
    #pragma unroll
    for (int k = 0; k < 6; k++) p[tid + k * 256] = fmaxf(v[k] * inv, 0.0f);
}

// per-channel sums/sumsq over each half.  grid (256, 2).
__global__ void bn_stats_kernel(const float* __restrict__ out) {
    int stream = blockIdx.y;
    int chunk = blockIdx.x;
    const float* base = out + (size_t)stream * HHALF + (size_t)chunk * 128 * C_;
    int tid = threadIdx.x;
    float s[6] = {}, q[6] = {};
    for (int r = 0; r < 128; r++) {
        const float* p = base + (size_t)r * C_;
        #pragma unroll
        for (int k = 0; k < 6; k++) {
            float v = p[tid + k * 256];
            s[k] += v; q[k] += v * v;
        }
    }
    #pragma unroll
    for (int k = 0; k < 6; k++) {
        atomicAdd(&g_sums [stream * C_ + tid + k * 256], s[k]);
        atomicAdd(&g_sumsq[stream * C_ + tid + k * 256], q[k]);
    }
}

__global__ void bn_finalize_kernel(const float* __restrict__ gamma,
                                   const float* __restrict__ beta) {
    int i = blockIdx.x * 256 + threadIdx.x;
    if (i < 2 * C_) {
        int c = (i >= C_) ? (i - C_) : i;
        float m = g_sums[i] * (1.0f / MROWS);
        float var = g_sumsq[i] * (1.0f / MROWS) - m * m;
        float sc = gamma[c] * rsqrtf(var + 1e-5f);
        g_scalev[i] = sc;
        g_shiftv[i] = beta[c] - m * sc;
    }
}

__global__ void bn_apply_kernel(float* __restrict__ out) {
    size_t row = blockIdx.x;
    int stream = (row >= (size_t)MROWS) ? 1 : 0;
    float* p = out + row * (size_t)C_;
    const float* sc = g_scalev + stream * C_;
    const float* sh = g_shiftv + stream * C_;
    int tid = threadIdx.x;
    #pragma unroll
    for (int k = 0; k < 6; k++) {
        int c = tid + k * 256;
        p[c] = p[c] * sc[c] + sh[c];
    }
}

// ---------------- launch ----------------
extern "C" void kernel_launch(void* const* d_in, const int* in_sizes, int n_in,
                              void* d_out, int out_size) {
    const float* x1    = (const float*)d_in[0];
    const float* x2    = (const float*)d_in[1];
    const int*   adj1  = (const int*)  d_in[2];
    const int*   adj2  = (const int*)  d_in[3];
    const float* Wx    = (const float*)d_in[4];
    const float* bx    = (const float*)d_in[5];
    const float* Wn    = (const float*)d_in[6];
    const float* bnn   = (const float*)d_in[7];
    const float* Wr    = (const float*)d_in[8];
    const float* br    = (const float*)d_in[9];
    const float* gamma = (const float*)d_in[10];
    const float* beta  = (const float*)d_in[11];
    float* out  = (float*)d_out;
    float* out2 = out + (size_t)HHALF;

    zero_stats_kernel<<<12, 256>>>();
    norms_kernel<<<8192, 256>>>(x1, x2);
    neigh_kernel<<<8192, 256>>>(x1, x2, adj1, adj2);
    sim_gemm_kernel<<<dim3(4, 4, 8), 256>>>(x1, x2);
    softmax_row_kernel<<<4096, 256>>>();
    softmax_col_kernel<<<4096, 256>>>();
    mu_gemm_kernel<<<dim3(32, 4, 8), 256>>>(x1, x2, 0);
    mu_gemm_kernel<<<dim3(32, 4, 8), 256>>>(x1, x2, 1);
    // h1 = [Wx(x1), Wn(nb1), Wr(mu1)]
    lin_gemm_kernel<<<dim3(4, 256), 256>>>(x1, x2, Wx, bx,  out,        0);
    lin_gemm_kernel<<<dim3(4, 256), 256>>>(x1, x2, Wn, bnn, out  + 512, 1);
    lin_gemm_kernel<<<dim3(4, 256), 256>>>(x1, x2, Wr, br,  out  + 1024, 2);
    // h2 = [Wx(x2), Wn(nb2), Wr(mu2)]
    lin_gemm_kernel<<<dim3(4, 256), 256>>>(x1, x2, Wx, bx,  out2,        3);
    lin_gemm_kernel<<<dim3(4, 256), 256>>>(x1, x2, Wn, bnn, out2 + 512, 4);
    lin_gemm_kernel<<<dim3(4, 256), 256>>>(x1, x2, Wr, br,  out2 + 1024, 5);
    normrelu_kernel<<<65536, 256>>>(out);
    bn_stats_kernel<<<dim3(256, 2), 256>>>(out);
    bn_finalize_kernel<<<12, 256>>>(gamma, beta);
    bn_apply_kernel<<<65536, 256>>>(out);
}

// round 9
// speedup vs baseline: 2.0488x; 2.0488x over previous
#include <cuda_runtime.h>
#include <cuda_bf16.h>
#include <cstdint>
#include <math.h>

// ---------------- problem constants ----------------
#define B_   8
#define S_   512
#define P_   8
#define F_   512
#define D_   4096
#define O_   512
#define C_   1536
#define MROWS 32768
static const long long HHALF = 50331648ll;   // MROWS * C_

// ---------------- scratch ----------------
__device__ float g_x1t[16777216];   // [B, D, S]
__device__ float g_x2t[16777216];
__device__ float g_nb1[16777216];
__device__ float g_nb2[16777216];
__device__ float g_mu1[16777216];
__device__ float g_mu2[16777216];
__device__ float g_sim [2097152];
__device__ float g_att1[2097152];
__device__ float g_att2[2097152];   // [b][j][i]
__device__ float g_n1[4096];
__device__ float g_n2[4096];
__device__ float g_sums [3072];
__device__ float g_sumsq[3072];
__device__ float g_scalev[3072];
__device__ float g_shiftv[3072];

// ---------------- warp MMA primitives (base compute_103 compatible) --------
__device__ __forceinline__ void mma16816(float* c, const uint32_t* a, const uint32_t* b) {
    asm volatile(
        "mma.sync.aligned.m16n8k16.row.col.f32.bf16.bf16.f32 "
        "{%0,%1,%2,%3}, {%4,%5,%6,%7}, {%8,%9}, {%0,%1,%2,%3};"
        : "+f"(c[0]), "+f"(c[1]), "+f"(c[2]), "+f"(c[3])
        : "r"(a[0]), "r"(a[1]), "r"(a[2]), "r"(a[3]), "r"(b[0]), "r"(b[1]));
}
__device__ __forceinline__ void ldsm4(uint32_t* r, uint32_t addr) {
    asm volatile("ldmatrix.sync.aligned.m8n8.x4.shared.b16 {%0,%1,%2,%3}, [%4];"
                 : "=r"(r[0]), "=r"(r[1]), "=r"(r[2]), "=r"(r[3]) : "r"(addr));
}
__device__ __forceinline__ uint32_t smem_to_u32(const void* p) {
    uint32_t a;
    asm("{ .reg .u64 t; cvta.to.shared.u64 t, %1; cvt.u32.u64 %0, t; }" : "=r"(a) : "l"(p));
    return a;
}
__device__ __forceinline__ uint32_t pack2(__nv_bfloat16 a, __nv_bfloat16 b) {
    __nv_bfloat162 t = __halves2bfloat162(a, b);
    return *reinterpret_cast<uint32_t*>(&t);
}
__device__ __forceinline__ void split4(float4 v, uint2& h, uint2& l) {
    __nv_bfloat16 h0 = __float2bfloat16(v.x);
    __nv_bfloat16 h1 = __float2bfloat16(v.y);
    __nv_bfloat16 h2 = __float2bfloat16(v.z);
    __nv_bfloat16 h3 = __float2bfloat16(v.w);
    __nv_bfloat16 l0 = __float2bfloat16(v.x - __bfloat162float(h0));
    __nv_bfloat16 l1 = __float2bfloat16(v.y - __bfloat162float(h1));
    __nv_bfloat16 l2 = __float2bfloat16(v.z - __bfloat162float(h2));
    __nv_bfloat16 l3 = __float2bfloat16(v.w - __bfloat162float(h3));
    h.x = pack2(h0, h1); h.y = pack2(h2, h3);
    l.x = pack2(l0, l1); l.y = pack2(l2, l3);
}

// ---------------- GEMM core -------------------------------------------------
// CTA tile 128x128, Kchunk = 32 (bf16), hi/lo split (3-MMA), 2-stage smem.
// smem layout per stage: rows of 32 bf16 = 64B, padded stride 80B.
//   AH @0, AL @10240, BH @20480, BL @30720; stage stride 40960; total 81920.
#define STR     80
#define OFF_AL  10240u
#define OFF_BH  20480u
#define OFF_BL  30720u
#define STAGE   40960u
#define SMEM_BYTES 81920

// A: row-major [128 rows, K] (K-contiguous, stride lda)
// B: row-major [128 rows(n), K] (K-contiguous, stride ldb)
// acc[mt][nt][4]: warp (wm= w>>2 -> m 64, wn = w&3 -> n 32)
__device__ __forceinline__ void gemm_tile(const float* __restrict__ Ag, int lda,
                                          const float* __restrict__ Bg, int ldb,
                                          int K, char* smem, float acc[4][4][4]) {
    const int tid = threadIdx.x;
    const int l = tid & 31, w = tid >> 5;
    const int wm = w >> 2, wn = w & 3;
    const int sel = l >> 3, r = l & 7;
    const uint32_t sbase = smem_to_u32(smem);

    // global-load mapping: 8 threads per row (8B bf16 out per thread), 32 rows/pass
    const int prow = tid >> 3;      // 0..31
    const int pc4  = tid & 7;       // 0..7  (float4 index within row)
    const float* Ain = Ag + (size_t)prow * lda + pc4 * 4;
    const float* Bin = Bg + (size_t)prow * ldb + pc4 * 4;

    // ldmatrix per-lane base offsets
    const uint32_t aoff = (uint32_t)((wm * 64 + (sel & 1) * 8 + r) * STR + (sel >> 1) * 16);
    const uint32_t boff = (uint32_t)((wn * 32 + (sel >> 1) * 8 + r) * STR + (sel & 1) * 16);

    float4 pa[4], pb[4];
    #pragma unroll
    for (int p = 0; p < 4; ++p) {
        pa[p] = *reinterpret_cast<const float4*>(Ain + (size_t)(p * 32) * lda);
        pb[p] = *reinterpret_cast<const float4*>(Bin + (size_t)(p * 32) * ldb);
    }

    const int nch = K >> 5;
    for (int c = 0; c < nch; ++c) {
        char* st = smem + (uint32_t)(c & 1) * STAGE;
        __syncthreads();
        // store current chunk (hi/lo split)
        #pragma unroll
        for (int p = 0; p < 4; ++p) {
            uint32_t off = (uint32_t)((prow + p * 32) * STR + pc4 * 8);
            uint2 h, lo;
            split4(pa[p], h, lo);
            *reinterpret_cast<uint2*>(st + off)          = h;
            *reinterpret_cast<uint2*>(st + OFF_AL + off) = lo;
            split4(pb[p], h, lo);
            *reinterpret_cast<uint2*>(st + OFF_BH + off) = h;
            *reinterpret_cast<uint2*>(st + OFF_BL + off) = lo;
        }
        // prefetch next chunk
        if (c + 1 < nch) {
            #pragma unroll
            for (int p = 0; p < 4; ++p) {
                pa[p] = *reinterpret_cast<const float4*>(Ain + (size_t)(p * 32) * lda + (c + 1) * 32);
                pb[p] = *reinterpret_cast<const float4*>(Bin + (size_t)(p * 32) * ldb + (c + 1) * 32);
            }
        }
        __syncthreads();
        // compute on this stage: 2 k16 steps
        const uint32_t ss = sbase + (uint32_t)(c & 1) * STAGE;
        #pragma unroll
        for (int ks = 0; ks < 2; ++ks) {
            uint32_t ah[4][4], al[4][4];
            #pragma unroll
            for (int mt = 0; mt < 4; ++mt) {
                uint32_t ad = ss + aoff + (uint32_t)(mt * 16 * STR + ks * 32);
                ldsm4(ah[mt], ad);
                ldsm4(al[mt], ad + OFF_AL);
            }
            uint32_t bh[2][4], bl[2][4];
            #pragma unroll
            for (int hH = 0; hH < 2; ++hH) {
                uint32_t bd = ss + boff + (uint32_t)(hH * 16 * STR + ks * 32);
                ldsm4(bh[hH], bd + OFF_BH);
                ldsm4(bl[hH], bd + OFF_BL);
            }
            #pragma unroll
            for (int mt = 0; mt < 4; ++mt) {
                #pragma unroll
                for (int nt = 0; nt < 4; ++nt) {
                    const uint32_t* bhp = &bh[nt >> 1][(nt & 1) * 2];
                    const uint32_t* blp = &bl[nt >> 1][(nt & 1) * 2];
                    mma16816(acc[mt][nt], ah[mt], bhp);
                    mma16816(acc[mt][nt], ah[mt], blp);
                    mma16816(acc[mt][nt], al[mt], bhp);
                }
            }
        }
    }
}

// ---------------- GEMM kernels ----------------
// sim[b,i,j] = <x1f[b,i],x2f[b,j]> / max(n1*n2,1e-6). grid (4,4,8).
__global__ void __launch_bounds__(256) sim_mma_kernel(const float* __restrict__ x1,
                                                      const float* __restrict__ x2) {
    extern __shared__ char smem[];
    int b = blockIdx.z, m0 = blockIdx.y * 128, n0 = blockIdx.x * 128;
    float acc[4][4][4] = {};
    gemm_tile(x1 + ((size_t)b * S_ + m0) * D_, D_,
              x2 + ((size_t)b * S_ + n0) * D_, D_, D_, smem, acc);
    const int l = threadIdx.x & 31, w = threadIdx.x >> 5;
    const int wm = w >> 2, wn = w & 3, g = l >> 2, tig = l & 3;
    const float* n1 = g_n1 + b * S_;
    const float* n2 = g_n2 + b * S_;
    float* C = g_sim + (size_t)b * S_ * S_;
    #pragma unroll
    for (int mt = 0; mt < 4; ++mt) {
        int row0 = m0 + wm * 64 + mt * 16 + g;
        float nm0 = n1[row0], nm1 = n1[row0 + 8];
        #pragma unroll
        for (int nt = 0; nt < 4; ++nt) {
            int col = n0 + wn * 32 + nt * 8 + tig * 2;
            float d0 = n2[col], d1 = n2[col + 1];
            float2 v0, v1;
            v0.x = acc[mt][nt][0] / fmaxf(nm0 * d0, 1e-6f);
            v0.y = acc[mt][nt][1] / fmaxf(nm0 * d1, 1e-6f);
            v1.x = acc[mt][nt][2] / fmaxf(nm1 * d0, 1e-6f);
            v1.y = acc[mt][nt][3] / fmaxf(nm1 * d1, 1e-6f);
            *reinterpret_cast<float2*>(C + (size_t)row0 * S_ + col) = v0;
            *reinterpret_cast<float2*>(C + (size_t)(row0 + 8) * S_ + col) = v1;
        }
    }
}

// mu = x_self - att @ x_other.  grid (32,4,8).
__global__ void __launch_bounds__(256) mu_mma_kernel(const float* __restrict__ x1,
                                                     const float* __restrict__ x2, int t) {
    extern __shared__ char smem[];
    int b = blockIdx.z, m0 = blockIdx.y * 128, n0 = blockIdx.x * 128;
    const float* Aatt = (t ? g_att2 : g_att1) + ((size_t)b * S_ + m0) * S_;
    const float* Bt   = (t ? g_x1t : g_x2t) + ((size_t)b * D_ + n0) * S_;
    const float* Xs   = (t ? x2 : x1) + (size_t)b * S_ * D_;
    float* Cm         = (t ? g_mu2 : g_mu1) + (size_t)b * S_ * D_;
    float acc[4][4][4] = {};
    gemm_tile(Aatt, S_, Bt, S_, S_, smem, acc);
    const int l = threadIdx.x & 31, w = threadIdx.x >> 5;
    const int wm = w >> 2, wn = w & 3, g = l >> 2, tig = l & 3;
    #pragma unroll
    for (int mt = 0; mt < 4; ++mt) {
        int row0 = m0 + wm * 64 + mt * 16 + g;
        #pragma unroll
        for (int nt = 0; nt < 4; ++nt) {
            int col = n0 + wn * 32 + nt * 8 + tig * 2;
            const float2 x0 = *reinterpret_cast<const float2*>(Xs + (size_t)row0 * D_ + col);
            const float2 x1v = *reinterpret_cast<const float2*>(Xs + (size_t)(row0 + 8) * D_ + col);
            float2 v0, v1;
            v0.x = x0.x - acc[mt][nt][0];
            v0.y = x0.y - acc[mt][nt][1];
            v1.x = x1v.x - acc[mt][nt][2];
            v1.y = x1v.y - acc[mt][nt][3];
            *reinterpret_cast<float2*>(Cm + (size_t)row0 * D_ + col) = v0;
            *reinterpret_cast<float2*>(Cm + (size_t)(row0 + 8) * D_ + col) = v1;
        }
    }
}

// lin: out[st][m, seg*512+n] = A_sel[m,:]·W_seg[n,:] + bias.  grid (4,256,6).
__global__ void __launch_bounds__(256) lin_mma_kernel(const float* __restrict__ x1,
                                                      const float* __restrict__ x2,
                                                      const float* __restrict__ Wx,
                                                      const float* __restrict__ Wn,
                                                      const float* __restrict__ Wr,
                                                      const float* __restrict__ bx,
                                                      const float* __restrict__ bn,
                                                      const float* __restrict__ br,
                                                      float* __restrict__ out) {
    extern __shared__ char smem[];
    int n0 = blockIdx.x * 128, m0 = blockIdx.y * 128, sel = blockIdx.z;
    int st = sel / 3, seg = sel % 3;
    const float* Ab = sel == 0 ? x1 : sel == 1 ? g_nb1 : sel == 2 ? g_mu1
                    : sel == 3 ? x2 : sel == 4 ? g_nb2 : g_mu2;
    const float* W    = (seg == 0 ? Wx : seg == 1 ? Wn : Wr) + (size_t)n0 * F_;
    const float* bias = (seg == 0 ? bx : seg == 1 ? bn : br) + n0;
    float acc[4][4][4] = {};
    gemm_tile(Ab + (size_t)m0 * F_, F_, W, F_, F_, smem, acc);
    const int l = threadIdx.x & 31, w = threadIdx.x >> 5;
    const int wm = w >> 2, wn = w & 3, g = l >> 2, tig = l & 3;
    float* ob = out + (size_t)st * HHALF + (size_t)seg * 512;
    #pragma unroll
    for (int mt = 0; mt < 4; ++mt) {
        int row0 = m0 + wm * 64 + mt * 16 + g;
        #pragma unroll
        for (int nt = 0; nt < 4; ++nt) {
            int col = wn * 32 + nt * 8 + tig * 2;     // 0..127 within tile
            float b0 = bias[col], b1 = bias[col + 1];
            float2 v0, v1;
            v0.x = acc[mt][nt][0] + b0; v0.y = acc[mt][nt][1] + b1;
            v1.x = acc[mt][nt][2] + b0; v1.y = acc[mt][nt][3] + b1;
            *reinterpret_cast<float2*>(ob + (size_t)row0 * C_ + n0 + col) = v0;
            *reinterpret_cast<float2*>(ob + (size_t)(row0 + 8) * C_ + n0 + col) = v1;
        }
    }
}

// ---------------- reduction helpers ----------------
__device__ __forceinline__ float block_sum(float v) {
    __shared__ float red[8];
    #pragma unroll
    for (int o = 16; o; o >>= 1) v += __shfl_xor_sync(0xffffffffu, v, o);
    if ((threadIdx.x & 31) == 0) red[threadIdx.x >> 5] = v;
    __syncthreads();
    v = red[threadIdx.x & 7];
    #pragma unroll
    for (int o = 4; o; o >>= 1) v += __shfl_xor_sync(0xffffffffu, v, o);
    return v;
}
__device__ __forceinline__ float block_max(float v) {
    __shared__ float redm[8];
    #pragma unroll
    for (int o = 16; o; o >>= 1) v = fmaxf(v, __shfl_xor_sync(0xffffffffu, v, o));
    if ((threadIdx.x & 31) == 0) redm[threadIdx.x >> 5] = v;
    __syncthreads();
    v = redm[threadIdx.x & 7];
    #pragma unroll
    for (int o = 4; o; o >>= 1) v = fmaxf(v, __shfl_xor_sync(0xffffffffu, v, o));
    return v;
}

// ---------------- elementwise kernels ----------------
__global__ void zero_stats_kernel() {
    int i = blockIdx.x * 256 + threadIdx.x;
    if (i < 2 * C_) { g_sums[i] = 0.0f; g_sumsq[i] = 0.0f; }
}

__global__ void transpose_kernel(const float* __restrict__ x1, const float* __restrict__ x2) {
    __shared__ float t[32][33];
    int which = blockIdx.z >> 3, b = blockIdx.z & 7;
    const float* x = (which ? x2 : x1) + (size_t)b * S_ * D_;
    float* xt = (which ? g_x2t : g_x1t) + (size_t)b * D_ * S_;
    int d0 = blockIdx.x * 32, i0 = blockIdx.y * 32;
    int tx = threadIdx.x, ty = threadIdx.y;
    #pragma unroll
    for (int k = 0; k < 32; k += 8)
        t[ty + k][tx] = x[(size_t)(i0 + ty + k) * D_ + d0 + tx];
    __syncthreads();
    #pragma unroll
    for (int k = 0; k < 32; k += 8)
        xt[(size_t)(d0 + ty + k) * S_ + i0 + tx] = t[tx][ty + k];
}

__global__ void norms_kernel(const float* __restrict__ x1, const float* __restrict__ x2) {
    int blk = blockIdx.x;
    int t = blk >> 12, bi = blk & 4095;
    const float* x = (t ? x2 : x1) + (size_t)bi * D_;
    float s = 0.0f;
    for (int k = threadIdx.x; k < D_; k += 256) { float v = x[k]; s += v * v; }
    s = block_sum(s);
    if (threadIdx.x == 0) (t ? g_n2 : g_n1)[bi] = sqrtf(s);
}

__global__ void neigh_kernel(const float* __restrict__ x1, const float* __restrict__ x2,
                             const int* __restrict__ adj1, const int* __restrict__ adj2) {
    int blk = blockIdx.x;
    int t = blk >> 12, bi = blk & 4095;
    int b = bi >> 9, i = bi & 511;
    const int* adj = (t ? adj2 : adj1) + (size_t)(b * S_ + i) * S_;
    const float* x = (t ? x2 : x1) + (size_t)b * S_ * D_;
    float* nb = (t ? g_nb2 : g_nb1) + (size_t)bi * D_;
    __shared__ int row[S_];
    for (int j = threadIdx.x; j < S_; j += 256) row[j] = adj[j];
    __syncthreads();
    float acc[16];
    #pragma unroll
    for (int k = 0; k < 16; k++) acc[k] = 0.0f;
    int deg = 0;
    for (int j = 0; j < S_; j++) {
        if (row[j] > 0 && j != i) {
            deg++;
            const float* xr = x + (size_t)j * D_ + threadIdx.x;
            #pragma unroll
            for (int k = 0; k < 16; k++) acc[k] += xr[k * 256];
        }
    }
    float inv = 1.0f / (float)deg;
    #pragma unroll
    for (int k = 0; k < 16; k++) nb[threadIdx.x + k * 256] = acc[k] * inv;
}

__global__ void softmax_row_kernel() {
    int bi = blockIdx.x;
    const float* srow = g_sim + (size_t)bi * S_;
    float* drow = g_att1 + (size_t)bi * S_;
    int tid = threadIdx.x;
    float v0 = srow[tid], v1 = srow[tid + 256];
    float mx = block_max(fmaxf(v0, v1));
    float e0 = expf(v0 - mx), e1 = expf(v1 - mx);
    float s = block_sum(e0 + e1);
    float inv = 1.0f / s;
    drow[tid] = e0 * inv;
    drow[tid + 256] = e1 * inv;
}

__global__ void softmax_col_kernel() {
    int bi = blockIdx.x;
    int b = bi >> 9, j = bi & 511;
    const float* base = g_sim + (size_t)b * S_ * S_ + j;
    float* drow = g_att2 + (size_t)bi * S_;
    int tid = threadIdx.x;
    float v0 = base[(size_t)tid * S_];
    float v1 = base[(size_t)(tid + 256) * S_];
    float mx = block_max(fmaxf(v0, v1));
    float e0 = expf(v0 - mx), e1 = expf(v1 - mx);
    float s = block_sum(e0 + e1);
    float inv = 1.0f / s;
    drow[tid] = e0 * inv;
    drow[tid + 256] = e1 * inv;
}

// relu(h/||h||) in place + accumulate BN sums. grid 4096, 16 rows/block.
__global__ void normrelu_bn_kernel(float* __restrict__ out) {
    size_t row0 = (size_t)blockIdx.x * 16;
    int stream = (row0 >= (size_t)MROWS) ? 1 : 0;
    int tid = threadIdx.x;
    float s[6] = {}, q[6] = {};
    for (int rr = 0; rr < 16; ++rr) {
        float* p = out + (row0 + rr) * (size_t)C_;
        float v[6];
        float ss = 0.0f;
        #pragma unroll
        for (int k = 0; k < 6; k++) { v[k] = p[tid + k * 256]; ss += v[k] * v[k]; }
        ss = block_sum(ss);
        float inv = 1.0f / fmaxf(sqrtf(ss), 1e-12f);
        #pragma unroll
        for (int k = 0; k < 6; k++) {
            float y = fmaxf(v[k] * inv, 0.0f);
            p[tid + k * 256] = y;
            s[k] += y; q[k] += y * y;
        }
        __syncthreads();
    }
    #pragma unroll
    for (int k = 0; k < 6; k++) {
        atomicAdd(&g_sums [stream * C_ + tid + k * 256], s[k]);
        atomicAdd(&g_sumsq[stream * C_ + tid + k * 256], q[k]);
    }
}

__global__ void bn_finalize_kernel(const float* __restrict__ gamma,
                                   const float* __restrict__ beta) {
    int i = blockIdx.x * 256 + threadIdx.x;
    if (i < 2 * C_) {
        int c = (i >= C_) ? (i - C_) : i;
        float m = g_sums[i] * (1.0f / MROWS);
        float var = g_sumsq[i] * (1.0f / MROWS) - m * m;
        float sc = gamma[c] * rsqrtf(var + 1e-5f);
        g_scalev[i] = sc;
        g_shiftv[i] = beta[c] - m * sc;
    }
}

__global__ void bn_apply_kernel(float* __restrict__ out) {
    size_t row = blockIdx.x;
    int stream = (row >= (size_t)MROWS) ? 1 : 0;
    float* p = out + row * (size_t)C_;
    const float* sc = g_scalev + stream * C_;
    const float* sh = g_shiftv + stream * C_;
    int tid = threadIdx.x;
    #pragma unroll
    for (int k = 0; k < 6; k++) {
        int c = tid + k * 256;
        p[c] = p[c] * sc[c] + sh[c];
    }
}

// ---------------- launch ----------------
extern "C" void kernel_launch(void* const* d_in, const int* in_sizes, int n_in,
                              void* d_out, int out_size) {
    const float* x1    = (const float*)d_in[0];
    const float* x2    = (const float*)d_in[1];
    const int*   adj1  = (const int*)  d_in[2];
    const int*   adj2  = (const int*)  d_in[3];
    const float* Wx    = (const float*)d_in[4];
    const float* bx    = (const float*)d_in[5];
    const float* Wn    = (const float*)d_in[6];
    const float* bnn   = (const float*)d_in[7];
    const float* Wr    = (const float*)d_in[8];
    const float* br    = (const float*)d_in[9];
    const float* gamma = (const float*)d_in[10];
    const float* beta  = (const float*)d_in[11];
    float* out = (float*)d_out;

    cudaFuncSetAttribute(sim_mma_kernel, cudaFuncAttributeMaxDynamicSharedMemorySize, SMEM_BYTES);
    cudaFuncSetAttribute(mu_mma_kernel,  cudaFuncAttributeMaxDynamicSharedMemorySize, SMEM_BYTES);
    cudaFuncSetAttribute(lin_mma_kernel, cudaFuncAttributeMaxDynamicSharedMemorySize, SMEM_BYTES);

    zero_stats_kernel<<<12, 256>>>();
    transpose_kernel<<<dim3(128, 16, 16), dim3(32, 8)>>>(x1, x2);
    norms_kernel<<<8192, 256>>>(x1, x2);
    neigh_kernel<<<8192, 256>>>(x1, x2, adj1, adj2);
    sim_mma_kernel<<<dim3(4, 4, 8), 256, SMEM_BYTES>>>(x1, x2);
    softmax_row_kernel<<<4096, 256>>>();
    softmax_col_kernel<<<4096, 256>>>();
    mu_mma_kernel<<<dim3(32, 4, 8), 256, SMEM_BYTES>>>(x1, x2, 0);
    mu_mma_kernel<<<dim3(32, 4, 8), 256, SMEM_BYTES>>>(x1, x2, 1);
    lin_mma_kernel<<<dim3(4, 256, 6), 256, SMEM_BYTES>>>(x1, x2, Wx, Wn, Wr, bx, bnn, br, out);
    normrelu_bn_kernel<<<4096, 256>>>(out);
    bn_finalize_kernel<<<12, 256>>>(gamma, beta);
    bn_apply_kernel<<<65536, 256>>>(out);
}

// round 12
// speedup vs baseline: 2.8940x; 1.4125x over previous
#include <cuda_runtime.h>
#include <cuda_bf16.h>
#include <cstdint>
#include <math.h>

// ---------------- problem constants ----------------
#define B_   8
#define S_   512
#define P_   8
#define F_   512
#define D_   4096
#define O_   512
#define C_   1536
#define MROWS 32768
static const long long HHALF = 50331648ll;   // MROWS * C_

// ---------------- scratch (bf16 hi/lo pre-split operands) ----------------
// NOTE: explicit 256B alignment — cp.async.cg 16B requires 16B-aligned global
// addresses and __device__ arrays only guarantee elem alignment by default.
__device__ __align__(256) __nv_bfloat16 g_x1h[16777216], g_x1l[16777216];
__device__ __align__(256) __nv_bfloat16 g_x2h[16777216], g_x2l[16777216];
__device__ __align__(256) __nv_bfloat16 g_x1th[16777216], g_x1tl[16777216];   // [B, D, S]
__device__ __align__(256) __nv_bfloat16 g_x2th[16777216], g_x2tl[16777216];
__device__ __align__(256) __nv_bfloat16 g_nb1h[16777216], g_nb1l[16777216];
__device__ __align__(256) __nv_bfloat16 g_nb2h[16777216], g_nb2l[16777216];
__device__ __align__(256) __nv_bfloat16 g_mu1h[16777216], g_mu1l[16777216];
__device__ __align__(256) __nv_bfloat16 g_mu2h[16777216], g_mu2l[16777216];
__device__ __align__(256) __nv_bfloat16 g_a1h[2097152], g_a1l[2097152];
__device__ __align__(256) __nv_bfloat16 g_a2h[2097152], g_a2l[2097152];       // [b][j][i]
__device__ __align__(256) __nv_bfloat16 g_Wh[786432], g_Wl[786432];           // [Wx|Wn|Wr]
__device__ __align__(256) float g_sim[2097152];
__device__ __align__(256) float g_n1[4096], g_n2[4096];
__device__ __align__(256) int   g_nidx[4194304];   // 8192 rows x 512 cap
__device__ __align__(256) int   g_ndeg[8192];
__device__ __align__(256) float g_sums[3072], g_sumsq[3072], g_scalev[3072], g_shiftv[3072];

// ---------------- primitives ----------------
__device__ __forceinline__ void mma16816(float* c, const uint32_t* a, const uint32_t* b) {
    asm volatile(
        "mma.sync.aligned.m16n8k16.row.col.f32.bf16.bf16.f32 "
        "{%0,%1,%2,%3}, {%4,%5,%6,%7}, {%8,%9}, {%0,%1,%2,%3};"
        : "+f"(c[0]), "+f"(c[1]), "+f"(c[2]), "+f"(c[3])
        : "r"(a[0]), "r"(a[1]), "r"(a[2]), "r"(a[3]), "r"(b[0]), "r"(b[1]));
}
__device__ __forceinline__ void ldsm4(uint32_t* r, uint32_t addr) {
    asm volatile("ldmatrix.sync.aligned.m8n8.x4.shared.b16 {%0,%1,%2,%3}, [%4];"
                 : "=r"(r[0]), "=r"(r[1]), "=r"(r[2]), "=r"(r[3]) : "r"(addr));
}
__device__ __forceinline__ uint32_t smem_to_u32(const void* p) {
    uint32_t a;
    asm("{ .reg .u64 t; cvta.to.shared.u64 t, %1; cvt.u32.u64 %0, t; }" : "=r"(a) : "l"(p));
    return a;
}
__device__ __forceinline__ void cp16(uint32_t s, const void* g) {
    asm volatile("cp.async.cg.shared.global [%0], [%1], 16;"
                 :: "r"(s), "l"(__cvta_generic_to_global(g)) : "memory");
}
__device__ __forceinline__ void cp_commit() { asm volatile("cp.async.commit_group;" ::: "memory"); }
template<int N> __device__ __forceinline__ void cp_wait() {
    asm volatile("cp.async.wait_group %0;" :: "n"(N) : "memory");
}
__device__ __forceinline__ uint32_t pack2(__nv_bfloat16 a, __nv_bfloat16 b) {
    __nv_bfloat162 t = __halves2bfloat162(a, b);
    return *reinterpret_cast<uint32_t*>(&t);
}
__device__ __forceinline__ void split4(float4 v, uint2& h, uint2& l) {
    __nv_bfloat16 h0 = __float2bfloat16(v.x);
    __nv_bfloat16 h1 = __float2bfloat16(v.y);
    __nv_bfloat16 h2 = __float2bfloat16(v.z);
    __nv_bfloat16 h3 = __float2bfloat16(v.w);
    __nv_bfloat16 l0 = __float2bfloat16(v.x - __bfloat162float(h0));
    __nv_bfloat16 l1 = __float2bfloat16(v.y - __bfloat162float(h1));
    __nv_bfloat16 l2 = __float2bfloat16(v.z - __bfloat162float(h2));
    __nv_bfloat16 l3 = __float2bfloat16(v.w - __bfloat162float(h3));
    h.x = pack2(h0, h1); h.y = pack2(h2, h3);
    l.x = pack2(l0, l1); l.y = pack2(l2, l3);
}
__device__ __forceinline__ void split2(float a, float b, uint32_t& h, uint32_t& l) {
    __nv_bfloat16 h0 = __float2bfloat16(a), h1 = __float2bfloat16(b);
    h = pack2(h0, h1);
    l = pack2(__float2bfloat16(a - __bfloat162float(h0)),
              __float2bfloat16(b - __bfloat162float(h1)));
}

// ---------------- GEMM core: 128x128 tile, BK=64 bf16, cp.async 3-stage -----
// smem stage: Ah@0, Al@16K, Bh@32K, Bl@48K; 64KB/stage, 3 stages = 192KB.
#define TILE_B  16384u
#define STAGE_B 65536u
#define STG     3
#define SMEM_BYTES 196608

__device__ __forceinline__ void issue_chunk(uint32_t sb,
        const __nv_bfloat16* __restrict__ Ah, const __nv_bfloat16* __restrict__ Al, int lda,
        const __nv_bfloat16* __restrict__ Bh, const __nv_bfloat16* __restrict__ Bl, int ldb,
        int kpos) {
    const int tid = threadIdx.x;
    #pragma unroll
    for (int it = 0; it < 4; ++it) {
        int q = tid + it * 256;
        int r = q >> 3, c16 = q & 7;
        uint32_t soff = (uint32_t)(r * 128 + (((c16 ^ r) & 7) << 4));
        size_t go = (size_t)r * lda + kpos + c16 * 8;
        size_t gob = (size_t)r * ldb + kpos + c16 * 8;
        cp16(sb + soff,              Ah + go);
        cp16(sb + TILE_B + soff,     Al + go);
        cp16(sb + 2 * TILE_B + soff, Bh + gob);
        cp16(sb + 3 * TILE_B + soff, Bl + gob);
    }
}

__device__ __forceinline__ void gemm_core(
        const __nv_bfloat16* __restrict__ Ah, const __nv_bfloat16* __restrict__ Al, int lda,
        const __nv_bfloat16* __restrict__ Bh, const __nv_bfloat16* __restrict__ Bl, int ldb,
        int K, char* smem, float acc[4][4][4]) {
    const int tid = threadIdx.x;
    const int l = tid & 31, w = tid >> 5;
    const int wm = w >> 2, wn = w & 3;
    const int rl = l & 7, sel = l >> 3;
    const int a_selc = sel >> 1, b_selc = sel & 1;
    const uint32_t sbase = smem_to_u32(smem);
    const uint32_t a_base = (uint32_t)((wm * 64 + (sel & 1) * 8 + rl) * 128);
    const uint32_t b_base = (uint32_t)(2 * TILE_B + (wn * 32 + (sel >> 1) * 8 + rl) * 128);

    const int nch = K >> 6;
    #pragma unroll
    for (int p = 0; p < STG - 1; ++p) {
        if (p < nch) issue_chunk(sbase + p * STAGE_B, Ah, Al, lda, Bh, Bl, ldb, p * 64);
        cp_commit();
    }
    for (int c = 0; c < nch; ++c) {
        cp_wait<STG - 2>();
        __syncthreads();
        int nc = c + STG - 1;
        if (nc < nch)
            issue_chunk(sbase + (uint32_t)(nc % STG) * STAGE_B, Ah, Al, lda, Bh, Bl, ldb, nc * 64);
        cp_commit();
        const uint32_t ss = sbase + (uint32_t)(c % STG) * STAGE_B;
        #pragma unroll
        for (int ks = 0; ks < 4; ++ks) {
            uint32_t ah[4][4], alr[4][4], bh[2][4], blr[2][4];
            uint32_t acol = ((uint32_t)((ks * 2 + a_selc) ^ rl)) << 4;
            uint32_t bcol = ((uint32_t)((ks * 2 + b_selc) ^ rl)) << 4;
            #pragma unroll
            for (int mt = 0; mt < 4; ++mt) {
                uint32_t ad = ss + a_base + mt * 2048 + acol;
                ldsm4(ah[mt], ad);
                ldsm4(alr[mt], ad + TILE_B);
            }
            #pragma unroll
            for (int hH = 0; hH < 2; ++hH) {
                uint32_t bd = ss + b_base + hH * 2048 + bcol;
                ldsm4(bh[hH], bd);
                ldsm4(blr[hH], bd + TILE_B);
            }
            #pragma unroll
            for (int mt = 0; mt < 4; ++mt)
                #pragma unroll
                for (int nt = 0; nt < 4; ++nt) {
                    const uint32_t* bhp = &bh[nt >> 1][(nt & 1) * 2];
                    const uint32_t* blp = &blr[nt >> 1][(nt & 1) * 2];
                    mma16816(acc[mt][nt], ah[mt], bhp);
                    mma16816(acc[mt][nt], ah[mt], blp);
                    mma16816(acc[mt][nt], alr[mt], bhp);
                }
        }
    }
}

// ---------------- GEMM kernels ----------------
__global__ void __launch_bounds__(256) sim_mma_kernel() {
    extern __shared__ __align__(128) char smem[];
    int b = blockIdx.z, m0 = blockIdx.y * 128, n0 = blockIdx.x * 128;
    float acc[4][4][4] = {};
    size_t ao = ((size_t)b * S_ + m0) * D_, bo = ((size_t)b * S_ + n0) * D_;
    gemm_core(g_x1h + ao, g_x1l + ao, D_, g_x2h + bo, g_x2l + bo, D_, D_, smem, acc);
    const int l = threadIdx.x & 31, w = threadIdx.x >> 5;
    const int wm = w >> 2, wn = w & 3, g = l >> 2, tig = l & 3;
    const float* n1 = g_n1 + b * S_;
    const float* n2 = g_n2 + b * S_;
    float* C = g_sim + (size_t)b * S_ * S_;
    #pragma unroll
    for (int mt = 0; mt < 4; ++mt) {
        int row0 = m0 + wm * 64 + mt * 16 + g;
        float nm0 = n1[row0], nm1 = n1[row0 + 8];
        #pragma unroll
        for (int nt = 0; nt < 4; ++nt) {
            int col = n0 + wn * 32 + nt * 8 + tig * 2;
            float d0 = n2[col], d1 = n2[col + 1];
            float2 v0, v1;
            v0.x = acc[mt][nt][0] / fmaxf(nm0 * d0, 1e-6f);
            v0.y = acc[mt][nt][1] / fmaxf(nm0 * d1, 1e-6f);
            v1.x = acc[mt][nt][2] / fmaxf(nm1 * d0, 1e-6f);
            v1.y = acc[mt][nt][3] / fmaxf(nm1 * d1, 1e-6f);
            *reinterpret_cast<float2*>(C + (size_t)row0 * S_ + col) = v0;
            *reinterpret_cast<float2*>(C + (size_t)(row0 + 8) * S_ + col) = v1;
        }
    }
}

__global__ void __launch_bounds__(256) mu_mma_kernel(const float* __restrict__ x1,
                                                     const float* __restrict__ x2, int t) {
    extern __shared__ __align__(128) char smem[];
    int b = blockIdx.z, m0 = blockIdx.y * 128, n0 = blockIdx.x * 128;
    size_t ao = ((size_t)b * S_ + m0) * S_, bo = ((size_t)b * D_ + n0) * S_;
    const __nv_bfloat16* Ah = (t ? g_a2h : g_a1h) + ao;
    const __nv_bfloat16* Al = (t ? g_a2l : g_a1l) + ao;
    const __nv_bfloat16* Bh = (t ? g_x1th : g_x2th) + bo;
    const __nv_bfloat16* Bl = (t ? g_x1tl : g_x2tl) + bo;
    const float* Xs = (t ? x2 : x1) + (size_t)b * S_ * D_;
    __nv_bfloat16* Mh = (t ? g_mu2h : g_mu1h) + (size_t)b * S_ * D_;
    __nv_bfloat16* Ml = (t ? g_mu2l : g_mu1l) + (size_t)b * S_ * D_;
    float acc[4][4][4] = {};
    gemm_core(Ah, Al, S_, Bh, Bl, S_, S_, smem, acc);
    const int l = threadIdx.x & 31, w = threadIdx.x >> 5;
    const int wm = w >> 2, wn = w & 3, g = l >> 2, tig = l & 3;
    #pragma unroll
    for (int mt = 0; mt < 4; ++mt) {
        int row0 = m0 + wm * 64 + mt * 16 + g;
        #pragma unroll
        for (int nt = 0; nt < 4; ++nt) {
            int col = n0 + wn * 32 + nt * 8 + tig * 2;
            const float2 xa = *reinterpret_cast<const float2*>(Xs + (size_t)row0 * D_ + col);
            const float2 xb = *reinterpret_cast<const float2*>(Xs + (size_t)(row0 + 8) * D_ + col);
            uint32_t h, lo2;
            split2(xa.x - acc[mt][nt][0], xa.y - acc[mt][nt][1], h, lo2);
            *reinterpret_cast<uint32_t*>(Mh + (size_t)row0 * D_ + col) = h;
            *reinterpret_cast<uint32_t*>(Ml + (size_t)row0 * D_ + col) = lo2;
            split2(xb.x - acc[mt][nt][2], xb.y - acc[mt][nt][3], h, lo2);
            *reinterpret_cast<uint32_t*>(Mh + (size_t)(row0 + 8) * D_ + col) = h;
            *reinterpret_cast<uint32_t*>(Ml + (size_t)(row0 + 8) * D_ + col) = lo2;
        }
    }
}

__global__ void __launch_bounds__(256) lin_mma_kernel(const float* __restrict__ bx,
                                                      const float* __restrict__ bn,
                                                      const float* __restrict__ br,
                                                      float* __restrict__ out) {
    extern __shared__ __align__(128) char smem[];
    int n0 = blockIdx.x * 128, m0 = blockIdx.y * 128, sel = blockIdx.z;
    int st = sel / 3, seg = sel % 3;
    const __nv_bfloat16* Ah = sel == 0 ? g_x1h : sel == 1 ? g_nb1h : sel == 2 ? g_mu1h
                            : sel == 3 ? g_x2h : sel == 4 ? g_nb2h : g_mu2h;
    const __nv_bfloat16* Al = sel == 0 ? g_x1l : sel == 1 ? g_nb1l : sel == 2 ? g_mu1l
                            : sel == 3 ? g_x2l : sel == 4 ? g_nb2l : g_mu2l;
    const __nv_bfloat16* Wh = g_Wh + (size_t)seg * 262144 + (size_t)n0 * F_;
    const __nv_bfloat16* Wl = g_Wl + (size_t)seg * 262144 + (size_t)n0 * F_;
    const float* bias = (seg == 0 ? bx : seg == 1 ? bn : br) + n0;
    float acc[4][4][4] = {};
    gemm_core(Ah + (size_t)m0 * F_, Al + (size_t)m0 * F_, F_, Wh, Wl, F_, F_, smem, acc);
    const int l = threadIdx.x & 31, w = threadIdx.x >> 5;
    const int wm = w >> 2, wn = w & 3, g = l >> 2, tig = l & 3;
    float* ob = out + (size_t)st * HHALF + (size_t)seg * 512 + n0;
    #pragma unroll
    for (int mt = 0; mt < 4; ++mt) {
        int row0 = m0 + wm * 64 + mt * 16 + g;
        #pragma unroll
        for (int nt = 0; nt < 4; ++nt) {
            int col = wn * 32 + nt * 8 + tig * 2;
            float b0 = bias[col], b1 = bias[col + 1];
            float2 v0, v1;
            v0.x = acc[mt][nt][0] + b0; v0.y = acc[mt][nt][1] + b1;
            v1.x = acc[mt][nt][2] + b0; v1.y = acc[mt][nt][3] + b1;
            *reinterpret_cast<float2*>(ob + (size_t)row0 * C_ + col) = v0;
            *reinterpret_cast<float2*>(ob + (size_t)(row0 + 8) * C_ + col) = v1;
        }
    }
}

// ---------------- reduction helpers ----------------
__device__ __forceinline__ float block_sum(float v) {
    __shared__ float red[8];
    #pragma unroll
    for (int o = 16; o; o >>= 1) v += __shfl_xor_sync(0xffffffffu, v, o);
    if ((threadIdx.x & 31) == 0) red[threadIdx.x >> 5] = v;
    __syncthreads();
    v = red[threadIdx.x & 7];
    #pragma unroll
    for (int o = 4; o; o >>= 1) v += __shfl_xor_sync(0xffffffffu, v, o);
    return v;
}
__device__ __forceinline__ float block_max(float v) {
    __shared__ float redm[8];
    #pragma unroll
    for (int o = 16; o; o >>= 1) v = fmaxf(v, __shfl_xor_sync(0xffffffffu, v, o));
    if ((threadIdx.x & 31) == 0) redm[threadIdx.x >> 5] = v;
    __syncthreads();
    v = redm[threadIdx.x & 7];
    #pragma unroll
    for (int o = 4; o; o >>= 1) v = fmaxf(v, __shfl_xor_sync(0xffffffffu, v, o));
    return v;
}

// ---------------- preprocessing kernels ----------------
__global__ void zero_stats_kernel() {
    int i = blockIdx.x * 256 + threadIdx.x;
    if (i < 2 * C_) { g_sums[i] = 0.0f; g_sumsq[i] = 0.0f; }
}

// split x into bf16 hi/lo + fused row norms. grid 8192, 256 thr.
__global__ void convert_x_kernel(const float* __restrict__ x1, const float* __restrict__ x2) {
    int blk = blockIdx.x;
    int t = blk >> 12, bi = blk & 4095;
    const float* x = (t ? x2 : x1) + (size_t)bi * D_;
    __nv_bfloat16* xh = (t ? g_x2h : g_x1h) + (size_t)bi * D_;
    __nv_bfloat16* xl = (t ? g_x2l : g_x1l) + (size_t)bi * D_;
    int tid = threadIdx.x;
    float ss = 0.0f;
    #pragma unroll
    for (int j = 0; j < 4; ++j) {
        int p = (tid + j * 256) * 4;
        float4 v = *reinterpret_cast<const float4*>(x + p);
        ss += v.x * v.x + v.y * v.y + v.z * v.z + v.w * v.w;
        uint2 h, lo;
        split4(v, h, lo);
        *reinterpret_cast<uint2*>(xh + p) = h;
        *reinterpret_cast<uint2*>(xl + p) = lo;
    }
    ss = block_sum(ss);
    if (tid == 0) (t ? g_n2 : g_n1)[bi] = sqrtf(ss);
}

// split weights. grid 3072, 256.
__global__ void convert_w_kernel(const float* __restrict__ Wx, const float* __restrict__ Wn,
                                 const float* __restrict__ Wr) {
    int i = blockIdx.x * 256 + threadIdx.x;          // < 786432
    int seg = i >> 18, off = i & 262143;
    float v = (seg == 0 ? Wx : seg == 1 ? Wn : Wr)[off];
    __nv_bfloat16 h = __float2bfloat16(v);
    g_Wh[i] = h;
    g_Wl[i] = __float2bfloat16(v - __bfloat162float(h));
}

// x [*,S,D] -> xT [*,D,S] bf16 hi/lo. grid (128,16,16), block (32,8).
__global__ void transpose_kernel(const float* __restrict__ x1, const float* __restrict__ x2) {
    __shared__ float t[32][33];
    int which = blockIdx.z >> 3, b = blockIdx.z & 7;
    const float* x = (which ? x2 : x1) + (size_t)b * S_ * D_;
    __nv_bfloat16* xth = (which ? g_x2th : g_x1th) + (size_t)b * D_ * S_;
    __nv_bfloat16* xtl = (which ? g_x2tl : g_x1tl) + (size_t)b * D_ * S_;
    int d0 = blockIdx.x * 32, i0 = blockIdx.y * 32;
    int tx = threadIdx.x, ty = threadIdx.y;
    #pragma unroll
    for (int k = 0; k < 32; k += 8)
        t[ty + k][tx] = x[(size_t)(i0 + ty + k) * D_ + d0 + tx];
    __syncthreads();
    #pragma unroll
    for (int k = 0; k < 32; k += 8) {
        float v = t[tx][ty + k];
        __nv_bfloat16 h = __float2bfloat16(v);
        size_t o = (size_t)(d0 + ty + k) * S_ + i0 + tx;
        xth[o] = h;
        xtl[o] = __float2bfloat16(v - __bfloat162float(h));
    }
}

// build neighbor index lists. one warp per (t,b,i). grid 1024, 256.
__global__ void neigh_idx_kernel(const int* __restrict__ adj1, const int* __restrict__ adj2) {
    int row = blockIdx.x * 8 + (threadIdx.x >> 5);
    int lane = threadIdx.x & 31;
    int t = row >> 12, bi = row & 4095;
    int b = bi >> 9, i = bi & 511;
    const int* arow = (t ? adj2 : adj1) + ((size_t)b * S_ + i) * S_;
    int* lst = g_nidx + (size_t)row * 512;
    int cnt = 0;
    for (int jj = lane; jj < S_; jj += 32) {
        bool f = (arow[jj] > 0) && (jj != i);
        unsigned m = __ballot_sync(0xffffffffu, f);
        if (f) lst[cnt + __popc(m & ((1u << lane) - 1))] = jj;
        cnt += __popc(m);
    }
    if (lane == 0) g_ndeg[row] = cnt;
}

// gather-mean via index lists, write bf16 hi/lo. grid 8192, 256.
__global__ void neigh_gather_kernel(const float* __restrict__ x1, const float* __restrict__ x2) {
    int blk = blockIdx.x;
    int t = blk >> 12, bi = blk & 4095;
    int b = bi >> 9;
    const float* x = (t ? x2 : x1) + (size_t)b * S_ * D_;
    __nv_bfloat16* nh = (t ? g_nb2h : g_nb1h) + (size_t)bi * D_;
    __nv_bfloat16* nl = (t ? g_nb2l : g_nb1l) + (size_t)bi * D_;
    int tid = threadIdx.x;
    __shared__ int sidx[512];
    __shared__ int sdeg;
    if (tid == 0) sdeg = g_ndeg[blk];
    __syncthreads();
    int deg = sdeg;
    for (int k = tid; k < deg; k += 256) sidx[k] = g_nidx[(size_t)blk * 512 + k];
    __syncthreads();
    float4 acc[4];
    #pragma unroll
    for (int j = 0; j < 4; ++j) acc[j] = make_float4(0.f, 0.f, 0.f, 0.f);
    for (int k = 0; k < deg; ++k) {
        const float* xr = x + (size_t)sidx[k] * D_;
        #pragma unroll
        for (int j = 0; j < 4; ++j) {
            float4 v = *reinterpret_cast<const float4*>(xr + (tid + j * 256) * 4);
            acc[j].x += v.x; acc[j].y += v.y; acc[j].z += v.z; acc[j].w += v.w;
        }
    }
    float inv = 1.0f / (float)deg;
    #pragma unroll
    for (int j = 0; j < 4; ++j) {
        int p = (tid + j * 256) * 4;
        float4 v = make_float4(acc[j].x * inv, acc[j].y * inv, acc[j].z * inv, acc[j].w * inv);
        uint2 h, lo;
        split4(v, h, lo);
        *reinterpret_cast<uint2*>(nh + p) = h;
        *reinterpret_cast<uint2*>(nl + p) = lo;
    }
}

// softmax over rows of sim -> att1 bf16 hi/lo. grid 4096.
__global__ void softmax_row_kernel() {
    int bi = blockIdx.x;
    const float* srow = g_sim + (size_t)bi * S_;
    __nv_bfloat16* dh = g_a1h + (size_t)bi * S_;
    __nv_bfloat16* dl = g_a1l + (size_t)bi * S_;
    int tid = threadIdx.x;
    float v0 = srow[tid], v1 = srow[tid + 256];
    float mx = block_max(fmaxf(v0, v1));
    float e0 = expf(v0 - mx), e1 = expf(v1 - mx);
    float s = block_sum(e0 + e1);
    float inv = 1.0f / s;
    float a0 = e0 * inv, a1 = e1 * inv;
    __nv_bfloat16 h0 = __float2bfloat16(a0), h1 = __float2bfloat16(a1);
    dh[tid] = h0;        dl[tid] = __float2bfloat16(a0 - __bfloat162float(h0));
    dh[tid + 256] = h1;  dl[tid + 256] = __float2bfloat16(a1 - __bfloat162float(h1));
}

// column softmax (stored transposed) -> att2 bf16 hi/lo. grid 4096.
__global__ void softmax_col_kernel() {
    int bi = blockIdx.x;
    int b = bi >> 9, j = bi & 511;
    const float* base = g_sim + (size_t)b * S_ * S_ + j;
    __nv_bfloat16* dh = g_a2h + (size_t)bi * S_;
    __nv_bfloat16* dl = g_a2l + (size_t)bi * S_;
    int tid = threadIdx.x;
    float v0 = base[(size_t)tid * S_];
    float v1 = base[(size_t)(tid + 256) * S_];
    float mx = block_max(fmaxf(v0, v1));
    float e0 = expf(v0 - mx), e1 = expf(v1 - mx);
    float s = block_sum(e0 + e1);
    float inv = 1.0f / s;
    float a0 = e0 * inv, a1 = e1 * inv;
    __nv_bfloat16 h0 = __float2bfloat16(a0), h1 = __float2bfloat16(a1);
    dh[tid] = h0;        dl[tid] = __float2bfloat16(a0 - __bfloat162float(h0));
    dh[tid + 256] = h1;  dl[tid + 256] = __float2bfloat16(a1 - __bfloat162float(h1));
}

// relu(h/||h||) in place + BN sums. grid 4096 (16 rows/block).
__global__ void normrelu_bn_kernel(float* __restrict__ out) {
    size_t row0 = (size_t)blockIdx.x * 16;
    int stream = (row0 >= (size_t)MROWS) ? 1 : 0;
    int tid = threadIdx.x;
    float s[6] = {}, q[6] = {};
    for (int rr = 0; rr < 16; ++rr) {
        float* p = out + (row0 + rr) * (size_t)C_;
        float v[6];
        float ss = 0.0f;
        #pragma unroll
        for (int k = 0; k < 6; k++) { v[k] = p[tid + k * 256]; ss += v[k] * v[k]; }
        ss = block_sum(ss);
        float inv = 1.0f / fmaxf(sqrtf(ss), 1e-12f);
        #pragma unroll
        for (int k = 0; k < 6; k++) {
            float y = fmaxf(v[k] * inv, 0.0f);
            p[tid + k * 256] = y;
            s[k] += y; q[k] += y * y;
        }
        __syncthreads();
    }
    #pragma unroll
    for (int k = 0; k < 6; k++) {
        atomicAdd(&g_sums [stream * C_ + tid + k * 256], s[k]);
        atomicAdd(&g_sumsq[stream * C_ + tid + k * 256], q[k]);
    }
}

__global__ void bn_finalize_kernel(const float* __restrict__ gamma,
                                   const float* __restrict__ beta) {
    int i = blockIdx.x * 256 + threadIdx.x;
    if (i < 2 * C_) {
        int c = (i >= C_) ? (i - C_) : i;
        float m = g_sums[i] * (1.0f / MROWS);
        float var = g_sumsq[i] * (1.0f / MROWS) - m * m;
        float sc = gamma[c] * rsqrtf(var + 1e-5f);
        g_scalev[i] = sc;
        g_shiftv[i] = beta[c] - m * sc;
    }
}

__global__ void bn_apply_kernel(float* __restrict__ out) {
    size_t row = blockIdx.x;
    int stream = (row >= (size_t)MROWS) ? 1 : 0;
    float* p = out + row * (size_t)C_;
    const float* sc = g_scalev + stream * C_;
    const float* sh = g_shiftv + stream * C_;
    int tid = threadIdx.x;
    #pragma unroll
    for (int k = 0; k < 6; k++) {
        int c = tid + k * 256;
        p[c] = p[c] * sc[c] + sh[c];
    }
}

// ---------------- launch ----------------
extern "C" void kernel_launch(void* const* d_in, const int* in_sizes, int n_in,
                              void* d_out, int out_size) {
    const float* x1    = (const float*)d_in[0];
    const float* x2    = (const float*)d_in[1];
    const int*   adj1  = (const int*)  d_in[2];
    const int*   adj2  = (const int*)  d_in[3];
    const float* Wx    = (const float*)d_in[4];
    const float* bx    = (const float*)d_in[5];
    const float* Wn    = (const float*)d_in[6];
    const float* bnn   = (const float*)d_in[7];
    const float* Wr    = (const float*)d_in[8];
    const float* br    = (const float*)d_in[9];
    const float* gamma = (const float*)d_in[10];
    const float* beta  = (const float*)d_in[11];
    float* out = (float*)d_out;

    cudaFuncSetAttribute(sim_mma_kernel, cudaFuncAttributeMaxDynamicSharedMemorySize, SMEM_BYTES);
    cudaFuncSetAttribute(mu_mma_kernel,  cudaFuncAttributeMaxDynamicSharedMemorySize, SMEM_BYTES);
    cudaFuncSetAttribute(lin_mma_kernel, cudaFuncAttributeMaxDynamicSharedMemorySize, SMEM_BYTES);

    zero_stats_kernel<<<12, 256>>>();
    convert_x_kernel<<<8192, 256>>>(x1, x2);
    convert_w_kernel<<<3072, 256>>>(Wx, Wn, Wr);
    transpose_kernel<<<dim3(128, 16, 16), dim3(32, 8)>>>(x1, x2);
    neigh_idx_kernel<<<1024, 256>>>(adj1, adj2);
    neigh_gather_kernel<<<8192, 256>>>(x1, x2);
    sim_mma_kernel<<<dim3(4, 4, 8), 256, SMEM_BYTES>>>();
    softmax_row_kernel<<<4096, 256>>>();
    softmax_col_kernel<<<4096, 256>>>();
    mu_mma_kernel<<<dim3(32, 4, 8), 256, SMEM_BYTES>>>(x1, x2, 0);
    mu_mma_kernel<<<dim3(32, 4, 8), 256, SMEM_BYTES>>>(x1, x2, 1);
    lin_mma_kernel<<<dim3(4, 256, 6), 256, SMEM_BYTES>>>(bx, bnn, br, out);
    normrelu_bn_kernel<<<4096, 256>>>(out);
    bn_finalize_kernel<<<12, 256>>>(gamma, beta);
    bn_apply_kernel<<<65536, 256>>>(out);
}

// round 13
// speedup vs baseline: 3.0326x; 1.0479x over previous
#include <cuda_runtime.h>
#include <cuda_bf16.h>
#include <cstdint>
#include <math.h>

// ---------------- problem constants ----------------
#define B_   8
#define S_   512
#define P_   8
#define F_   512
#define D_   4096
#define O_   512
#define C_   1536
#define MROWS 32768
static const long long HHALF = 50331648ll;   // MROWS * C_

// ---------------- scratch (bf16 hi/lo pre-split operands) ----------------
__device__ __align__(256) __nv_bfloat16 g_x1h[16777216], g_x1l[16777216];
__device__ __align__(256) __nv_bfloat16 g_x2h[16777216], g_x2l[16777216];
__device__ __align__(256) __nv_bfloat16 g_x1th[16777216], g_x1tl[16777216];   // [B, D, S]
__device__ __align__(256) __nv_bfloat16 g_x2th[16777216], g_x2tl[16777216];
__device__ __align__(256) __nv_bfloat16 g_nb1h[16777216], g_nb1l[16777216];
__device__ __align__(256) __nv_bfloat16 g_nb2h[16777216], g_nb2l[16777216];
__device__ __align__(256) __nv_bfloat16 g_mu1h[16777216], g_mu1l[16777216];
__device__ __align__(256) __nv_bfloat16 g_mu2h[16777216], g_mu2l[16777216];
__device__ __align__(256) __nv_bfloat16 g_a1h[2097152], g_a1l[2097152];
__device__ __align__(256) __nv_bfloat16 g_a2h[2097152], g_a2l[2097152];       // [b][j][i]
__device__ __align__(256) __nv_bfloat16 g_Wh[786432], g_Wl[786432];           // [Wx|Wn|Wr]
__device__ __align__(256) float g_sim[2097152];
__device__ __align__(256) float g_n1[4096], g_n2[4096];
__device__ __align__(256) int   g_nidx[4194304];   // 8192 rows x 512 cap
__device__ __align__(256) int   g_ndeg[8192];
__device__ __align__(256) float g_rinv[65536];
__device__ __align__(256) float g_sums[3072], g_sumsq[3072], g_scalev[3072], g_shiftv[3072];

// ---------------- primitives ----------------
__device__ __forceinline__ void mma16816(float* c, const uint32_t* a, const uint32_t* b) {
    asm volatile(
        "mma.sync.aligned.m16n8k16.row.col.f32.bf16.bf16.f32 "
        "{%0,%1,%2,%3}, {%4,%5,%6,%7}, {%8,%9}, {%0,%1,%2,%3};"
        : "+f"(c[0]), "+f"(c[1]), "+f"(c[2]), "+f"(c[3])
        : "r"(a[0]), "r"(a[1]), "r"(a[2]), "r"(a[3]), "r"(b[0]), "r"(b[1]));
}
__device__ __forceinline__ void ldsm4(uint32_t* r, uint32_t addr) {
    asm volatile("ldmatrix.sync.aligned.m8n8.x4.shared.b16 {%0,%1,%2,%3}, [%4];"
                 : "=r"(r[0]), "=r"(r[1]), "=r"(r[2]), "=r"(r[3]) : "r"(addr));
}
__device__ __forceinline__ uint32_t smem_to_u32(const void* p) {
    uint32_t a;
    asm("{ .reg .u64 t; cvta.to.shared.u64 t, %1; cvt.u32.u64 %0, t; }" : "=r"(a) : "l"(p));
    return a;
}
__device__ __forceinline__ void cp16(uint32_t s, const void* g) {
    asm volatile("cp.async.cg.shared.global [%0], [%1], 16;"
                 :: "r"(s), "l"(__cvta_generic_to_global(g)) : "memory");
}
__device__ __forceinline__ void cp_commit() { asm volatile("cp.async.commit_group;" ::: "memory"); }
template<int N> __device__ __forceinline__ void cp_wait() {
    asm volatile("cp.async.wait_group %0;" :: "n"(N) : "memory");
}
__device__ __forceinline__ uint32_t pack2(__nv_bfloat16 a, __nv_bfloat16 b) {
    __nv_bfloat162 t = __halves2bfloat162(a, b);
    return *reinterpret_cast<uint32_t*>(&t);
}
__device__ __forceinline__ void split4(float4 v, uint2& h, uint2& l) {
    __nv_bfloat16 h0 = __float2bfloat16(v.x);
    __nv_bfloat16 h1 = __float2bfloat16(v.y);
    __nv_bfloat16 h2 = __float2bfloat16(v.z);
    __nv_bfloat16 h3 = __float2bfloat16(v.w);
    __nv_bfloat16 l0 = __float2bfloat16(v.x - __bfloat162float(h0));
    __nv_bfloat16 l1 = __float2bfloat16(v.y - __bfloat162float(h1));
    __nv_bfloat16 l2 = __float2bfloat16(v.z - __bfloat162float(h2));
    __nv_bfloat16 l3 = __float2bfloat16(v.w - __bfloat162float(h3));
    h.x = pack2(h0, h1); h.y = pack2(h2, h3);
    l.x = pack2(l0, l1); l.y = pack2(l2, l3);
}
__device__ __forceinline__ void split2(float a, float b, uint32_t& h, uint32_t& l) {
    __nv_bfloat16 h0 = __float2bfloat16(a), h1 = __float2bfloat16(b);
    h = pack2(h0, h1);
    l = pack2(__float2bfloat16(a - __bfloat162float(h0)),
              __float2bfloat16(b - __bfloat162float(h1)));
}

// ---------------- GEMM core: 128x128 tile, BK=64 bf16, cp.async 3-stage -----
#define TILE_B  16384u
#define STAGE_B 65536u
#define STG     3
#define SMEM_BYTES 196608

__device__ __forceinline__ void issue_chunk(uint32_t sb,
        const __nv_bfloat16* __restrict__ Ah, const __nv_bfloat16* __restrict__ Al, int lda,
        const __nv_bfloat16* __restrict__ Bh, const __nv_bfloat16* __restrict__ Bl, int ldb,
        int kpos) {
    const int tid = threadIdx.x;
    #pragma unroll
    for (int it = 0; it < 4; ++it) {
        int q = tid + it * 256;
        int r = q >> 3, c16 = q & 7;
        uint32_t soff = (uint32_t)(r * 128 + (((c16 ^ r) & 7) << 4));
        size_t go = (size_t)r * lda + kpos + c16 * 8;
        size_t gob = (size_t)r * ldb + kpos + c16 * 8;
        cp16(sb + soff,              Ah + go);
        cp16(sb + TILE_B + soff,     Al + go);
        cp16(sb + 2 * TILE_B + soff, Bh + gob);
        cp16(sb + 3 * TILE_B + soff, Bl + gob);
    }
}

__device__ __forceinline__ void gemm_core(
        const __nv_bfloat16* __restrict__ Ah, const __nv_bfloat16* __restrict__ Al, int lda,
        const __nv_bfloat16* __restrict__ Bh, const __nv_bfloat16* __restrict__ Bl, int ldb,
        int K, char* smem, float acc[4][4][4]) {
    const int tid = threadIdx.x;
    const int l = tid & 31, w = tid >> 5;
    const int wm = w >> 2, wn = w & 3;
    const int rl = l & 7, sel = l >> 3;
    const int a_selc = sel >> 1, b_selc = sel & 1;
    const uint32_t sbase = smem_to_u32(smem);
    const uint32_t a_base = (uint32_t)((wm * 64 + (sel & 1) * 8 + rl) * 128);
    const uint32_t b_base = (uint32_t)(2 * TILE_B + (wn * 32 + (sel >> 1) * 8 + rl) * 128);

    const int nch = K >> 6;
    #pragma unroll
    for (int p = 0; p < STG - 1; ++p) {
        if (p < nch) issue_chunk(sbase + p * STAGE_B, Ah, Al, lda, Bh, Bl, ldb, p * 64);
        cp_commit();
    }
    for (int c = 0; c < nch; ++c) {
        cp_wait<STG - 2>();
        __syncthreads();
        int nc = c + STG - 1;
        if (nc < nch)
            issue_chunk(sbase + (uint32_t)(nc % STG) * STAGE_B, Ah, Al, lda, Bh, Bl, ldb, nc * 64);
        cp_commit();
        const uint32_t ss = sbase + (uint32_t)(c % STG) * STAGE_B;
        #pragma unroll
        for (int ks = 0; ks < 4; ++ks) {
            uint32_t ah[4][4], alr[4][4], bh[2][4], blr[2][4];
            uint32_t acol = ((uint32_t)((ks * 2 + a_selc) ^ rl)) << 4;
            uint32_t bcol = ((uint32_t)((ks * 2 + b_selc) ^ rl)) << 4;
            #pragma unroll
            for (int mt = 0; mt < 4; ++mt) {
                uint32_t ad = ss + a_base + mt * 2048 + acol;
                ldsm4(ah[mt], ad);
                ldsm4(alr[mt], ad + TILE_B);
            }
            #pragma unroll
            for (int hH = 0; hH < 2; ++hH) {
                uint32_t bd = ss + b_base + hH * 2048 + bcol;
                ldsm4(bh[hH], bd);
                ldsm4(blr[hH], bd + TILE_B);
            }
            #pragma unroll
            for (int mt = 0; mt < 4; ++mt)
                #pragma unroll
                for (int nt = 0; nt < 4; ++nt) {
                    const uint32_t* bhp = &bh[nt >> 1][(nt & 1) * 2];
                    const uint32_t* blp = &blr[nt >> 1][(nt & 1) * 2];
                    mma16816(acc[mt][nt], ah[mt], bhp);
                    mma16816(acc[mt][nt], ah[mt], blp);
                    mma16816(acc[mt][nt], alr[mt], bhp);
                }
        }
    }
}

// ---------------- GEMM kernels ----------------
__global__ void __launch_bounds__(256) sim_mma_kernel() {
    extern __shared__ __align__(128) char smem[];
    int b = blockIdx.z, m0 = blockIdx.y * 128, n0 = blockIdx.x * 128;
    float acc[4][4][4] = {};
    size_t ao = ((size_t)b * S_ + m0) * D_, bo = ((size_t)b * S_ + n0) * D_;
    gemm_core(g_x1h + ao, g_x1l + ao, D_, g_x2h + bo, g_x2l + bo, D_, D_, smem, acc);
    const int l = threadIdx.x & 31, w = threadIdx.x >> 5;
    const int wm = w >> 2, wn = w & 3, g = l >> 2, tig = l & 3;
    const float* n1 = g_n1 + b * S_;
    const float* n2 = g_n2 + b * S_;
    float* C = g_sim + (size_t)b * S_ * S_;
    #pragma unroll
    for (int mt = 0; mt < 4; ++mt) {
        int row0 = m0 + wm * 64 + mt * 16 + g;
        float nm0 = n1[row0], nm1 = n1[row0 + 8];
        #pragma unroll
        for (int nt = 0; nt < 4; ++nt) {
            int col = n0 + wn * 32 + nt * 8 + tig * 2;
            float d0 = n2[col], d1 = n2[col + 1];
            float2 v0, v1;
            v0.x = acc[mt][nt][0] / fmaxf(nm0 * d0, 1e-6f);
            v0.y = acc[mt][nt][1] / fmaxf(nm0 * d1, 1e-6f);
            v1.x = acc[mt][nt][2] / fmaxf(nm1 * d0, 1e-6f);
            v1.y = acc[mt][nt][3] / fmaxf(nm1 * d1, 1e-6f);
            *reinterpret_cast<float2*>(C + (size_t)row0 * S_ + col) = v0;
            *reinterpret_cast<float2*>(C + (size_t)(row0 + 8) * S_ + col) = v1;
        }
    }
}

__global__ void __launch_bounds__(256) mu_mma_kernel(const float* __restrict__ x1,
                                                     const float* __restrict__ x2, int t) {
    extern __shared__ __align__(128) char smem[];
    int b = blockIdx.z, m0 = blockIdx.y * 128, n0 = blockIdx.x * 128;
    size_t ao = ((size_t)b * S_ + m0) * S_, bo = ((size_t)b * D_ + n0) * S_;
    const __nv_bfloat16* Ah = (t ? g_a2h : g_a1h) + ao;
    const __nv_bfloat16* Al = (t ? g_a2l : g_a1l) + ao;
    const __nv_bfloat16* Bh = (t ? g_x1th : g_x2th) + bo;
    const __nv_bfloat16* Bl = (t ? g_x1tl : g_x2tl) + bo;
    const float* Xs = (t ? x2 : x1) + (size_t)b * S_ * D_;
    __nv_bfloat16* Mh = (t ? g_mu2h : g_mu1h) + (size_t)b * S_ * D_;
    __nv_bfloat16* Ml = (t ? g_mu2l : g_mu1l) + (size_t)b * S_ * D_;
    float acc[4][4][4] = {};
    gemm_core(Ah, Al, S_, Bh, Bl, S_, S_, smem, acc);
    const int l = threadIdx.x & 31, w = threadIdx.x >> 5;
    const int wm = w >> 2, wn = w & 3, g = l >> 2, tig = l & 3;
    #pragma unroll
    for (int mt = 0; mt < 4; ++mt) {
        int row0 = m0 + wm * 64 + mt * 16 + g;
        #pragma unroll
        for (int nt = 0; nt < 4; ++nt) {
            int col = n0 + wn * 32 + nt * 8 + tig * 2;
            const float2 xa = *reinterpret_cast<const float2*>(Xs + (size_t)row0 * D_ + col);
            const float2 xb = *reinterpret_cast<const float2*>(Xs + (size_t)(row0 + 8) * D_ + col);
            uint32_t h, lo2;
            split2(xa.x - acc[mt][nt][0], xa.y - acc[mt][nt][1], h, lo2);
            *reinterpret_cast<uint32_t*>(Mh + (size_t)row0 * D_ + col) = h;
            *reinterpret_cast<uint32_t*>(Ml + (size_t)row0 * D_ + col) = lo2;
            split2(xb.x - acc[mt][nt][2], xb.y - acc[mt][nt][3], h, lo2);
            *reinterpret_cast<uint32_t*>(Mh + (size_t)(row0 + 8) * D_ + col) = h;
            *reinterpret_cast<uint32_t*>(Ml + (size_t)(row0 + 8) * D_ + col) = lo2;
        }
    }
}

__global__ void __launch_bounds__(256) lin_mma_kernel(const float* __restrict__ bx,
                                                      const float* __restrict__ bn,
                                                      const float* __restrict__ br,
                                                      float* __restrict__ out) {
    extern __shared__ __align__(128) char smem[];
    int n0 = blockIdx.x * 128, m0 = blockIdx.y * 128, sel = blockIdx.z;
    int st = sel / 3, seg = sel % 3;
    const __nv_bfloat16* Ah = sel == 0 ? g_x1h : sel == 1 ? g_nb1h : sel == 2 ? g_mu1h
                            : sel == 3 ? g_x2h : sel == 4 ? g_nb2h : g_mu2h;
    const __nv_bfloat16* Al = sel == 0 ? g_x1l : sel == 1 ? g_nb1l : sel == 2 ? g_mu1l
                            : sel == 3 ? g_x2l : sel == 4 ? g_nb2l : g_mu2l;
    const __nv_bfloat16* Wh = g_Wh + (size_t)seg * 262144 + (size_t)n0 * F_;
    const __nv_bfloat16* Wl = g_Wl + (size_t)seg * 262144 + (size_t)n0 * F_;
    const float* bias = (seg == 0 ? bx : seg == 1 ? bn : br) + n0;
    float acc[4][4][4] = {};
    gemm_core(Ah + (size_t)m0 * F_, Al + (size_t)m0 * F_, F_, Wh, Wl, F_, F_, smem, acc);
    const int l = threadIdx.x & 31, w = threadIdx.x >> 5;
    const int wm = w >> 2, wn = w & 3, g = l >> 2, tig = l & 3;
    float* ob = out + (size_t)st * HHALF + (size_t)seg * 512 + n0;
    #pragma unroll
    for (int mt = 0; mt < 4; ++mt) {
        int row0 = m0 + wm * 64 + mt * 16 + g;
        #pragma unroll
        for (int nt = 0; nt < 4; ++nt) {
            int col = wn * 32 + nt * 8 + tig * 2;
            float b0 = bias[col], b1 = bias[col + 1];
            float2 v0, v1;
            v0.x = acc[mt][nt][0] + b0; v0.y = acc[mt][nt][1] + b1;
            v1.x = acc[mt][nt][2] + b0; v1.y = acc[mt][nt][3] + b1;
            *reinterpret_cast<float2*>(ob + (size_t)row0 * C_ + col) = v0;
            *reinterpret_cast<float2*>(ob + (size_t)(row0 + 8) * C_ + col) = v1;
        }
    }
}

// ---------------- reduction helpers ----------------
__device__ __forceinline__ float block_sum(float v) {
    __shared__ float red[8];
    #pragma unroll
    for (int o = 16; o; o >>= 1) v += __shfl_xor_sync(0xffffffffu, v, o);
    if ((threadIdx.x & 31) == 0) red[threadIdx.x >> 5] = v;
    __syncthreads();
    v = red[threadIdx.x & 7];
    #pragma unroll
    for (int o = 4; o; o >>= 1) v += __shfl_xor_sync(0xffffffffu, v, o);
    return v;
}
__device__ __forceinline__ float block_max(float v) {
    __shared__ float redm[8];
    #pragma unroll
    for (int o = 16; o; o >>= 1) v = fmaxf(v, __shfl_xor_sync(0xffffffffu, v, o));
    if ((threadIdx.x & 31) == 0) redm[threadIdx.x >> 5] = v;
    __syncthreads();
    v = redm[threadIdx.x & 7];
    #pragma unroll
    for (int o = 4; o; o >>= 1) v = fmaxf(v, __shfl_xor_sync(0xffffffffu, v, o));
    return v;
}

// ---------------- preprocessing kernels ----------------
__global__ void zero_stats_kernel() {
    int i = blockIdx.x * 256 + threadIdx.x;
    if (i < 2 * C_) { g_sums[i] = 0.0f; g_sumsq[i] = 0.0f; }
}

__global__ void convert_x_kernel(const float* __restrict__ x1, const float* __restrict__ x2) {
    int blk = blockIdx.x;
    int t = blk >> 12, bi = blk & 4095;
    const float* x = (t ? x2 : x1) + (size_t)bi * D_;
    __nv_bfloat16* xh = (t ? g_x2h : g_x1h) + (size_t)bi * D_;
    __nv_bfloat16* xl = (t ? g_x2l : g_x1l) + (size_t)bi * D_;
    int tid = threadIdx.x;
    float ss = 0.0f;
    #pragma unroll
    for (int j = 0; j < 4; ++j) {
        int p = (tid + j * 256) * 4;
        float4 v = *reinterpret_cast<const float4*>(x + p);
        ss += v.x * v.x + v.y * v.y + v.z * v.z + v.w * v.w;
        uint2 h, lo;
        split4(v, h, lo);
        *reinterpret_cast<uint2*>(xh + p) = h;
        *reinterpret_cast<uint2*>(xl + p) = lo;
    }
    ss = block_sum(ss);
    if (tid == 0) (t ? g_n2 : g_n1)[bi] = sqrtf(ss);
}

__global__ void convert_w_kernel(const float* __restrict__ Wx, const float* __restrict__ Wn,
                                 const float* __restrict__ Wr) {
    int i = blockIdx.x * 256 + threadIdx.x;          // < 786432
    int seg = i >> 18, off = i & 262143;
    float v = (seg == 0 ? Wx : seg == 1 ? Wn : Wr)[off];
    __nv_bfloat16 h = __float2bfloat16(v);
    g_Wh[i] = h;
    g_Wl[i] = __float2bfloat16(v - __bfloat162float(h));
}

__global__ void transpose_kernel(const float* __restrict__ x1, const float* __restrict__ x2) {
    __shared__ float t[32][33];
    int which = blockIdx.z >> 3, b = blockIdx.z & 7;
    const float* x = (which ? x2 : x1) + (size_t)b * S_ * D_;
    __nv_bfloat16* xth = (which ? g_x2th : g_x1th) + (size_t)b * D_ * S_;
    __nv_bfloat16* xtl = (which ? g_x2tl : g_x1tl) + (size_t)b * D_ * S_;
    int d0 = blockIdx.x * 32, i0 = blockIdx.y * 32;
    int tx = threadIdx.x, ty = threadIdx.y;
    #pragma unroll
    for (int k = 0; k < 32; k += 8)
        t[ty + k][tx] = x[(size_t)(i0 + ty + k) * D_ + d0 + tx];
    __syncthreads();
    #pragma unroll
    for (int k = 0; k < 32; k += 8) {
        float v = t[tx][ty + k];
        __nv_bfloat16 h = __float2bfloat16(v);
        size_t o = (size_t)(d0 + ty + k) * S_ + i0 + tx;
        xth[o] = h;
        xtl[o] = __float2bfloat16(v - __bfloat162float(h));
    }
}

__global__ void neigh_idx_kernel(const int* __restrict__ adj1, const int* __restrict__ adj2) {
    int row = blockIdx.x * 8 + (threadIdx.x >> 5);
    int lane = threadIdx.x & 31;
    int t = row >> 12, bi = row & 4095;
    int b = bi >> 9, i = bi & 511;
    const int* arow = (t ? adj2 : adj1) + ((size_t)b * S_ + i) * S_;
    int* lst = g_nidx + (size_t)row * 512;
    int cnt = 0;
    for (int jj = lane; jj < S_; jj += 32) {
        bool f = (arow[jj] > 0) && (jj != i);
        unsigned m = __ballot_sync(0xffffffffu, f);
        if (f) lst[cnt + __popc(m & ((1u << lane) - 1))] = jj;
        cnt += __popc(m);
    }
    if (lane == 0) g_ndeg[row] = cnt;
}

__global__ void neigh_gather_kernel(const float* __restrict__ x1, const float* __restrict__ x2) {
    int blk = blockIdx.x;
    int t = blk >> 12, bi = blk & 4095;
    int b = bi >> 9;
    const float* x = (t ? x2 : x1) + (size_t)b * S_ * D_;
    __nv_bfloat16* nh = (t ? g_nb2h : g_nb1h) + (size_t)bi * D_;
    __nv_bfloat16* nl = (t ? g_nb2l : g_nb1l) + (size_t)bi * D_;
    int tid = threadIdx.x;
    __shared__ int sidx[512];
    __shared__ int sdeg;
    if (tid == 0) sdeg = g_ndeg[blk];
    __syncthreads();
    int deg = sdeg;
    for (int k = tid; k < deg; k += 256) sidx[k] = g_nidx[(size_t)blk * 512 + k];
    __syncthreads();
    float4 acc[4];
    #pragma unroll
    for (int j = 0; j < 4; ++j) acc[j] = make_float4(0.f, 0.f, 0.f, 0.f);
    for (int k = 0; k < deg; ++k) {
        const float* xr = x + (size_t)sidx[k] * D_;
        #pragma unroll
        for (int j = 0; j < 4; ++j) {
            float4 v = *reinterpret_cast<const float4*>(xr + (tid + j * 256) * 4);
            acc[j].x += v.x; acc[j].y += v.y; acc[j].z += v.z; acc[j].w += v.w;
        }
    }
    float inv = 1.0f / (float)deg;
    #pragma unroll
    for (int j = 0; j < 4; ++j) {
        int p = (tid + j * 256) * 4;
        float4 v = make_float4(acc[j].x * inv, acc[j].y * inv, acc[j].z * inv, acc[j].w * inv);
        uint2 h, lo;
        split4(v, h, lo);
        *reinterpret_cast<uint2*>(nh + p) = h;
        *reinterpret_cast<uint2*>(nl + p) = lo;
    }
}

__global__ void softmax_row_kernel() {
    int bi = blockIdx.x;
    const float* srow = g_sim + (size_t)bi * S_;
    __nv_bfloat16* dh = g_a1h + (size_t)bi * S_;
    __nv_bfloat16* dl = g_a1l + (size_t)bi * S_;
    int tid = threadIdx.x;
    float v0 = srow[tid], v1 = srow[tid + 256];
    float mx = block_max(fmaxf(v0, v1));
    float e0 = expf(v0 - mx), e1 = expf(v1 - mx);
    float s = block_sum(e0 + e1);
    float inv = 1.0f / s;
    float a0 = e0 * inv, a1 = e1 * inv;
    __nv_bfloat16 h0 = __float2bfloat16(a0), h1 = __float2bfloat16(a1);
    dh[tid] = h0;        dl[tid] = __float2bfloat16(a0 - __bfloat162float(h0));
    dh[tid + 256] = h1;  dl[tid + 256] = __float2bfloat16(a1 - __bfloat162float(h1));
}

__global__ void softmax_col_kernel() {
    int bi = blockIdx.x;
    int b = bi >> 9, j = bi & 511;
    const float* base = g_sim + (size_t)b * S_ * S_ + j;
    __nv_bfloat16* dh = g_a2h + (size_t)bi * S_;
    __nv_bfloat16* dl = g_a2l + (size_t)bi * S_;
    int tid = threadIdx.x;
    float v0 = base[(size_t)tid * S_];
    float v1 = base[(size_t)(tid + 256) * S_];
    float mx = block_max(fmaxf(v0, v1));
    float e0 = expf(v0 - mx), e1 = expf(v1 - mx);
    float s = block_sum(e0 + e1);
    float inv = 1.0f / s;
    float a0 = e0 * inv, a1 = e1 * inv;
    __nv_bfloat16 h0 = __float2bfloat16(a0), h1 = __float2bfloat16(a1);
    dh[tid] = h0;        dl[tid] = __float2bfloat16(a0 - __bfloat162float(h0));
    dh[tid + 256] = h1;  dl[tid + 256] = __float2bfloat16(a1 - __bfloat162float(h1));
}

// stats pass: compute rinv per row + channel sums of y=relu(h*rinv). NO y write.
__global__ void normrelu_stats_kernel(const float* __restrict__ out) {
    size_t row0 = (size_t)blockIdx.x * 16;
    int stream = (row0 >= (size_t)MROWS) ? 1 : 0;
    int tid = threadIdx.x;
    float s[6] = {}, q[6] = {};
    for (int rr = 0; rr < 16; ++rr) {
        const float* p = out + (row0 + rr) * (size_t)C_;
        float v[6];
        float ss = 0.0f;
        #pragma unroll
        for (int k = 0; k < 6; k++) { v[k] = p[tid + k * 256]; ss += v[k] * v[k]; }
        ss = block_sum(ss);
        float inv = 1.0f / fmaxf(sqrtf(ss), 1e-12f);
        if (tid == 0) g_rinv[row0 + rr] = inv;
        #pragma unroll
        for (int k = 0; k < 6; k++) {
            float y = fmaxf(v[k] * inv, 0.0f);
            s[k] += y; q[k] += y * y;
        }
        __syncthreads();
    }
    #pragma unroll
    for (int k = 0; k < 6; k++) {
        atomicAdd(&g_sums [stream * C_ + tid + k * 256], s[k]);
        atomicAdd(&g_sumsq[stream * C_ + tid + k * 256], q[k]);
    }
}

__global__ void bn_finalize_kernel(const float* __restrict__ gamma,
                                   const float* __restrict__ beta) {
    int i = blockIdx.x * 256 + threadIdx.x;
    if (i < 2 * C_) {
        int c = (i >= C_) ? (i - C_) : i;
        float m = g_sums[i] * (1.0f / MROWS);
        float var = g_sumsq[i] * (1.0f / MROWS) - m * m;
        float sc = gamma[c] * rsqrtf(var + 1e-5f);
        g_scalev[i] = sc;
        g_shiftv[i] = beta[c] - m * sc;
    }
}

// fused: y = relu(h*rinv); out = y*sc + sh. one read + one write. 384 thr.
__global__ void bn_apply_kernel(float* __restrict__ out) {
    size_t row = blockIdx.x;
    int stream = (row >= (size_t)MROWS) ? 1 : 0;
    float rinv = g_rinv[row];
    float4* p = reinterpret_cast<float4*>(out + row * (size_t)C_);
    const float4* sc = reinterpret_cast<const float4*>(g_scalev + stream * C_);
    const float4* sh = reinterpret_cast<const float4*>(g_shiftv + stream * C_);
    int tid = threadIdx.x;          // 0..383, 384*4 = 1536
    float4 h = p[tid], s4 = sc[tid], b4 = sh[tid];
    float4 o;
    o.x = fmaxf(h.x * rinv, 0.0f) * s4.x + b4.x;
    o.y = fmaxf(h.y * rinv, 0.0f) * s4.y + b4.y;
    o.z = fmaxf(h.z * rinv, 0.0f) * s4.z + b4.z;
    o.w = fmaxf(h.w * rinv, 0.0f) * s4.w + b4.w;
    p[tid] = o;
}

// ---------------- launch ----------------
extern "C" void kernel_launch(void* const* d_in, const int* in_sizes, int n_in,
                              void* d_out, int out_size) {
    const float* x1    = (const float*)d_in[0];
    const float* x2    = (const float*)d_in[1];
    const int*   adj1  = (const int*)  d_in[2];
    const int*   adj2  = (const int*)  d_in[3];
    const float* Wx    = (const float*)d_in[4];
    const float* bx    = (const float*)d_in[5];
    const float* Wn    = (const float*)d_in[6];
    const float* bnn   = (const float*)d_in[7];
    const float* Wr    = (const float*)d_in[8];
    const float* br    = (const float*)d_in[9];
    const float* gamma = (const float*)d_in[10];
    const float* beta  = (const float*)d_in[11];
    float* out = (float*)d_out;

    static cudaStream_t s1 = []() {
        cudaStream_t s; cudaStreamCreateWithFlags(&s, cudaStreamNonBlocking); return s;
    }();
    static cudaEvent_t ev_root = []() {
        cudaEvent_t e; cudaEventCreateWithFlags(&e, cudaEventDisableTiming); return e;
    }();
    static cudaEvent_t ev_tr = []() {
        cudaEvent_t e; cudaEventCreateWithFlags(&e, cudaEventDisableTiming); return e;
    }();
    static cudaEvent_t ev_side = []() {
        cudaEvent_t e; cudaEventCreateWithFlags(&e, cudaEventDisableTiming); return e;
    }();

    cudaFuncSetAttribute(sim_mma_kernel, cudaFuncAttributeMaxDynamicSharedMemorySize, SMEM_BYTES);
    cudaFuncSetAttribute(mu_mma_kernel,  cudaFuncAttributeMaxDynamicSharedMemorySize, SMEM_BYTES);
    cudaFuncSetAttribute(lin_mma_kernel, cudaFuncAttributeMaxDynamicSharedMemorySize, SMEM_BYTES);

    // fork side stream off the captured (legacy) stream
    cudaEventRecord(ev_root, 0);
    cudaStreamWaitEvent(s1, ev_root, 0);

    // side chain: independent of sim path
    zero_stats_kernel<<<12, 256, 0, s1>>>();
    transpose_kernel<<<dim3(128, 16, 16), dim3(32, 8), 0, s1>>>(x1, x2);
    cudaEventRecord(ev_tr, s1);
    neigh_idx_kernel<<<1024, 256, 0, s1>>>(adj1, adj2);
    neigh_gather_kernel<<<8192, 256, 0, s1>>>(x1, x2);
    convert_w_kernel<<<3072, 256, 0, s1>>>(Wx, Wn, Wr);
    cudaEventRecord(ev_side, s1);

    // main chain
    convert_x_kernel<<<8192, 256>>>(x1, x2);
    sim_mma_kernel<<<dim3(4, 4, 8), 256, SMEM_BYTES>>>();
    softmax_row_kernel<<<4096, 256>>>();
    softmax_col_kernel<<<4096, 256>>>();
    cudaStreamWaitEvent(0, ev_tr, 0);
    mu_mma_kernel<<<dim3(32, 4, 8), 256, SMEM_BYTES>>>(x1, x2, 0);
    mu_mma_kernel<<<dim3(32, 4, 8), 256, SMEM_BYTES>>>(x1, x2, 1);
    cudaStreamWaitEvent(0, ev_side, 0);
    lin_mma_kernel<<<dim3(4, 256, 6), 256, SMEM_BYTES>>>(bx, bnn, br, out);
    normrelu_stats_kernel<<<4096, 256>>>(out);
    bn_finalize_kernel<<<12, 256>>>(gamma, beta);
    bn_apply_kernel<<<65536, 384>>>(out);
}

// round 15
// speedup vs baseline: 3.8593x; 1.2726x over previous
#include <cuda_runtime.h>
#include <cuda_fp16.h>
#include <cstdint>
#include <math.h>

// ---------------- problem constants ----------------
#define B_   8
#define S_   512
#define P_   8
#define F_   512
#define D_   4096
#define O_   512
#define C_   1536
#define MROWS 32768
static const long long HHALF = 50331648ll;   // MROWS * C_

// ---------------- scratch (fp16 hi/lo pre-split operands) ----------------
__device__ __align__(256) __half g_x1h[16777216], g_x1l[16777216];
__device__ __align__(256) __half g_x2h[16777216], g_x2l[16777216];
__device__ __align__(256) __half g_x1th[16777216];   // [B, D, S] hi only (B operand)
__device__ __align__(256) __half g_x2th[16777216];
__device__ __align__(256) __half g_nb1h[16777216], g_nb1l[16777216];
__device__ __align__(256) __half g_nb2h[16777216], g_nb2l[16777216];
__device__ __align__(256) __half g_mu1h[16777216], g_mu1l[16777216];
__device__ __align__(256) __half g_mu2h[16777216], g_mu2l[16777216];
__device__ __align__(256) __half g_a1h[2097152], g_a1l[2097152];
__device__ __align__(256) __half g_a2h[2097152], g_a2l[2097152];     // [b][j][i]
__device__ __align__(256) __half g_Wh[786432];                       // hi only (B operand)
__device__ __align__(256) float g_sim[2097152];
__device__ __align__(256) float g_n1[4096], g_n2[4096];
__device__ __align__(256) int   g_nidx[4194304];
__device__ __align__(256) int   g_ndeg[8192];
__device__ __align__(256) float g_rinv[65536];
__device__ __align__(256) float g_sums[3072], g_sumsq[3072], g_scalev[3072], g_shiftv[3072];

// ---------------- primitives ----------------
__device__ __forceinline__ void mma16816(float* c, const uint32_t* a, const uint32_t* b) {
    asm volatile(
        "mma.sync.aligned.m16n8k16.row.col.f32.f16.f16.f32 "
        "{%0,%1,%2,%3}, {%4,%5,%6,%7}, {%8,%9}, {%0,%1,%2,%3};"
        : "+f"(c[0]), "+f"(c[1]), "+f"(c[2]), "+f"(c[3])
        : "r"(a[0]), "r"(a[1]), "r"(a[2]), "r"(a[3]), "r"(b[0]), "r"(b[1]));
}
__device__ __forceinline__ void ldsm4(uint32_t* r, uint32_t addr) {
    asm volatile("ldmatrix.sync.aligned.m8n8.x4.shared.b16 {%0,%1,%2,%3}, [%4];"
                 : "=r"(r[0]), "=r"(r[1]), "=r"(r[2]), "=r"(r[3]) : "r"(addr));
}
__device__ __forceinline__ uint32_t smem_to_u32(const void* p) {
    uint32_t a;
    asm("{ .reg .u64 t; cvta.to.shared.u64 t, %1; cvt.u32.u64 %0, t; }" : "=r"(a) : "l"(p));
    return a;
}
__device__ __forceinline__ void cp16(uint32_t s, const void* g) {
    asm volatile("cp.async.cg.shared.global [%0], [%1], 16;"
                 :: "r"(s), "l"(__cvta_generic_to_global(g)) : "memory");
}
__device__ __forceinline__ void cp_commit() { asm volatile("cp.async.commit_group;" ::: "memory"); }
template<int N> __device__ __forceinline__ void cp_wait() {
    asm volatile("cp.async.wait_group %0;" :: "n"(N) : "memory");
}
__device__ __forceinline__ uint32_t pack2h(__half a, __half b) {
    __half2 t = __halves2half2(a, b);
    return *reinterpret_cast<uint32_t*>(&t);
}
__device__ __forceinline__ void split4h(float4 v, uint2& h, uint2& l) {
    __half h0 = __float2half(v.x), h1 = __float2half(v.y);
    __half h2 = __float2half(v.z), h3 = __float2half(v.w);
    __half l0 = __float2half(v.x - __half2float(h0));
    __half l1 = __float2half(v.y - __half2float(h1));
    __half l2 = __float2half(v.z - __half2float(h2));
    __half l3 = __float2half(v.w - __half2float(h3));
    h.x = pack2h(h0, h1); h.y = pack2h(h2, h3);
    l.x = pack2h(l0, l1); l.y = pack2h(l2, l3);
}
__device__ __forceinline__ void split2h(float a, float b, uint32_t& h, uint32_t& l) {
    __half h0 = __float2half(a), h1 = __float2half(b);
    h = pack2h(h0, h1);
    l = pack2h(__float2half(a - __half2float(h0)),
               __float2half(b - __half2float(h1)));
}

// ---------------- GEMM core: 128x128 tile, BK=64 fp16, A split, cp.async ----
// smem stage: Ah@0, Al@16K, Bh@32K; 48KB/stage, 3 stages = 144KB.
#define TILE_B  16384u
#define STAGE_B 49152u
#define STG     3
#define SMEM_BYTES 147456

__device__ __forceinline__ void issue_chunk(uint32_t sb,
        const __half* __restrict__ Ah, const __half* __restrict__ Al, int lda,
        const __half* __restrict__ Bh, int ldb, int kpos) {
    const int tid = threadIdx.x;
    #pragma unroll
    for (int it = 0; it < 4; ++it) {
        int q = tid + it * 256;
        int r = q >> 3, c16 = q & 7;
        uint32_t soff = (uint32_t)(r * 128 + (((c16 ^ r) & 7) << 4));
        size_t go = (size_t)r * lda + kpos + c16 * 8;
        size_t gob = (size_t)r * ldb + kpos + c16 * 8;
        cp16(sb + soff,              Ah + go);
        cp16(sb + TILE_B + soff,     Al + go);
        cp16(sb + 2 * TILE_B + soff, Bh + gob);
    }
}

__device__ __forceinline__ void gemm_core(
        const __half* __restrict__ Ah, const __half* __restrict__ Al, int lda,
        const __half* __restrict__ Bh, int ldb,
        int K, char* smem, float acc[4][4][4]) {
    const int tid = threadIdx.x;
    const int l = tid & 31, w = tid >> 5;
    const int wm = w >> 2, wn = w & 3;
    const int rl = l & 7, sel = l >> 3;
    const int a_selc = sel >> 1, b_selc = sel & 1;
    const uint32_t sbase = smem_to_u32(smem);
    const uint32_t a_base = (uint32_t)((wm * 64 + (sel & 1) * 8 + rl) * 128);
    const uint32_t b_base = (uint32_t)(2 * TILE_B + (wn * 32 + (sel >> 1) * 8 + rl) * 128);

    const int nch = K >> 6;
    #pragma unroll
    for (int p = 0; p < STG - 1; ++p) {
        if (p < nch) issue_chunk(sbase + p * STAGE_B, Ah, Al, lda, Bh, ldb, p * 64);
        cp_commit();
    }
    for (int c = 0; c < nch; ++c) {
        cp_wait<STG - 2>();
        __syncthreads();
        int nc = c + STG - 1;
        if (nc < nch)
            issue_chunk(sbase + (uint32_t)(nc % STG) * STAGE_B, Ah, Al, lda, Bh, ldb, nc * 64);
        cp_commit();
        const uint32_t ss = sbase + (uint32_t)(c % STG) * STAGE_B;
        #pragma unroll
        for (int ks = 0; ks < 4; ++ks) {
            uint32_t ah[4][4], alr[4][4], bh[2][4];
            uint32_t acol = ((uint32_t)((ks * 2 + a_selc) ^ rl)) << 4;
            uint32_t bcol = ((uint32_t)((ks * 2 + b_selc) ^ rl)) << 4;
            #pragma unroll
            for (int mt = 0; mt < 4; ++mt) {
                uint32_t ad = ss + a_base + mt * 2048 + acol;
                ldsm4(ah[mt], ad);
                ldsm4(alr[mt], ad + TILE_B);
            }
            #pragma unroll
            for (int hH = 0; hH < 2; ++hH) {
                uint32_t bd = ss + b_base + hH * 2048 + bcol;
                ldsm4(bh[hH], bd);
            }
            #pragma unroll
            for (int mt = 0; mt < 4; ++mt)
                #pragma unroll
                for (int nt = 0; nt < 4; ++nt) {
                    const uint32_t* bhp = &bh[nt >> 1][(nt & 1) * 2];
                    mma16816(acc[mt][nt], ah[mt], bhp);
                    mma16816(acc[mt][nt], alr[mt], bhp);
                }
        }
    }
}

// ---------------- GEMM kernels ----------------
__global__ void __launch_bounds__(256) sim_mma_kernel() {
    extern __shared__ __align__(128) char smem[];
    int b = blockIdx.z, m0 = blockIdx.y * 128, n0 = blockIdx.x * 128;
    float acc[4][4][4] = {};
    size_t ao = ((size_t)b * S_ + m0) * D_, bo = ((size_t)b * S_ + n0) * D_;
    gemm_core(g_x1h + ao, g_x1l + ao, D_, g_x2h + bo, D_, D_, smem, acc);
    const int l = threadIdx.x & 31, w = threadIdx.x >> 5;
    const int wm = w >> 2, wn = w & 3, g = l >> 2, tig = l & 3;
    const float* n1 = g_n1 + b * S_;
    const float* n2 = g_n2 + b * S_;
    float* C = g_sim + (size_t)b * S_ * S_;
    #pragma unroll
    for (int mt = 0; mt < 4; ++mt) {
        int row0 = m0 + wm * 64 + mt * 16 + g;
        float nm0 = n1[row0], nm1 = n1[row0 + 8];
        #pragma unroll
        for (int nt = 0; nt < 4; ++nt) {
            int col = n0 + wn * 32 + nt * 8 + tig * 2;
            float d0 = n2[col], d1 = n2[col + 1];
            float2 v0, v1;
            v0.x = acc[mt][nt][0] / fmaxf(nm0 * d0, 1e-6f);
            v0.y = acc[mt][nt][1] / fmaxf(nm0 * d1, 1e-6f);
            v1.x = acc[mt][nt][2] / fmaxf(nm1 * d0, 1e-6f);
            v1.y = acc[mt][nt][3] / fmaxf(nm1 * d1, 1e-6f);
            *reinterpret_cast<float2*>(C + (size_t)row0 * S_ + col) = v0;
            *reinterpret_cast<float2*>(C + (size_t)(row0 + 8) * S_ + col) = v1;
        }
    }
}

__global__ void __launch_bounds__(256) mu_mma_kernel(const float* __restrict__ x1,
                                                     const float* __restrict__ x2, int t) {
    extern __shared__ __align__(128) char smem[];
    int b = blockIdx.z, m0 = blockIdx.y * 128, n0 = blockIdx.x * 128;
    size_t ao = ((size_t)b * S_ + m0) * S_, bo = ((size_t)b * D_ + n0) * S_;
    const __half* Ah = (t ? g_a2h : g_a1h) + ao;
    const __half* Al = (t ? g_a2l : g_a1l) + ao;
    const __half* Bh = (t ? g_x1th : g_x2th) + bo;
    const float* Xs = (t ? x2 : x1) + (size_t)b * S_ * D_;
    __half* Mh = (t ? g_mu2h : g_mu1h) + (size_t)b * S_ * D_;
    __half* Ml = (t ? g_mu2l : g_mu1l) + (size_t)b * S_ * D_;
    float acc[4][4][4] = {};
    gemm_core(Ah, Al, S_, Bh, S_, S_, smem, acc);
    const int l = threadIdx.x & 31, w = threadIdx.x >> 5;
    const int wm = w >> 2, wn = w & 3, g = l >> 2, tig = l & 3;
    #pragma unroll
    for (int mt = 0; mt < 4; ++mt) {
        int row0 = m0 + wm * 64 + mt * 16 + g;
        #pragma unroll
        for (int nt = 0; nt < 4; ++nt) {
            int col = n0 + wn * 32 + nt * 8 + tig * 2;
            const float2 xa = *reinterpret_cast<const float2*>(Xs + (size_t)row0 * D_ + col);
            const float2 xb = *reinterpret_cast<const float2*>(Xs + (size_t)(row0 + 8) * D_ + col);
            uint32_t h, lo2;
            split2h(xa.x - acc[mt][nt][0], xa.y - acc[mt][nt][1], h, lo2);
            *reinterpret_cast<uint32_t*>(Mh + (size_t)row0 * D_ + col) = h;
            *reinterpret_cast<uint32_t*>(Ml + (size_t)row0 * D_ + col) = lo2;
            split2h(xb.x - acc[mt][nt][2], xb.y - acc[mt][nt][3], h, lo2);
            *reinterpret_cast<uint32_t*>(Mh + (size_t)(row0 + 8) * D_ + col) = h;
            *reinterpret_cast<uint32_t*>(Ml + (size_t)(row0 + 8) * D_ + col) = lo2;
        }
    }
}

// kind 0: z in 0..3 -> st=z>>1, seg=z&1 (x, nb).  kind 1: z in 0..1 -> st=z, seg=2 (mu).
__global__ void __launch_bounds__(256) lin_mma_kernel(const float* __restrict__ bx,
                                                      const float* __restrict__ bn,
                                                      const float* __restrict__ br,
                                                      float* __restrict__ out, int kind) {
    extern __shared__ __align__(128) char smem[];
    int n0 = blockIdx.x * 128, m0 = blockIdx.y * 128;
    int st, seg;
    if (kind == 0) { st = blockIdx.z >> 1; seg = blockIdx.z & 1; }
    else           { st = blockIdx.z;      seg = 2; }
    int sel = st * 3 + seg;
    const __half* Ah = sel == 0 ? g_x1h : sel == 1 ? g_nb1h : sel == 2 ? g_mu1h
                     : sel == 3 ? g_x2h : sel == 4 ? g_nb2h : g_mu2h;
    const __half* Al = sel == 0 ? g_x1l : sel == 1 ? g_nb1l : sel == 2 ? g_mu1l
                     : sel == 3 ? g_x2l : sel == 4 ? g_nb2l : g_mu2l;
    const __half* Wh = g_Wh + (size_t)seg * 262144 + (size_t)n0 * F_;
    const float* bias = (seg == 0 ? bx : seg == 1 ? bn : br) + n0;
    float acc[4][4][4] = {};
    gemm_core(Ah + (size_t)m0 * F_, Al + (size_t)m0 * F_, F_, Wh, F_, F_, smem, acc);
    const int l = threadIdx.x & 31, w = threadIdx.x >> 5;
    const int wm = w >> 2, wn = w & 3, g = l >> 2, tig = l & 3;
    float* ob = out + (size_t)st * HHALF + (size_t)seg * 512 + n0;
    #pragma unroll
    for (int mt = 0; mt < 4; ++mt) {
        int row0 = m0 + wm * 64 + mt * 16 + g;
        #pragma unroll
        for (int nt = 0; nt < 4; ++nt) {
            int col = wn * 32 + nt * 8 + tig * 2;
            float b0 = bias[col], b1 = bias[col + 1];
            float2 v0, v1;
            v0.x = acc[mt][nt][0] + b0; v0.y = acc[mt][nt][1] + b1;
            v1.x = acc[mt][nt][2] + b0; v1.y = acc[mt][nt][3] + b1;
            *reinterpret_cast<float2*>(ob + (size_t)row0 * C_ + col) = v0;
            *reinterpret_cast<float2*>(ob + (size_t)(row0 + 8) * C_ + col) = v1;
        }
    }
}

// ---------------- reduction helpers ----------------
__device__ __forceinline__ float block_sum(float v) {
    __shared__ float red[8];
    #pragma unroll
    for (int o = 16; o; o >>= 1) v += __shfl_xor_sync(0xffffffffu, v, o);
    if ((threadIdx.x & 31) == 0) red[threadIdx.x >> 5] = v;
    __syncthreads();
    v = red[threadIdx.x & 7];
    #pragma unroll
    for (int o = 4; o; o >>= 1) v += __shfl_xor_sync(0xffffffffu, v, o);
    return v;
}
__device__ __forceinline__ float block_max(float v) {
    __shared__ float redm[8];
    #pragma unroll
    for (int o = 16; o; o >>= 1) v = fmaxf(v, __shfl_xor_sync(0xffffffffu, v, o));
    if ((threadIdx.x & 31) == 0) redm[threadIdx.x >> 5] = v;
    __syncthreads();
    v = redm[threadIdx.x & 7];
    #pragma unroll
    for (int o = 4; o; o >>= 1) v = fmaxf(v, __shfl_xor_sync(0xffffffffu, v, o));
    return v;
}

// ---------------- preprocessing kernels ----------------
__global__ void zero_stats_kernel() {
    int i = blockIdx.x * 256 + threadIdx.x;
    if (i < 2 * C_) { g_sums[i] = 0.0f; g_sumsq[i] = 0.0f; }
}

__global__ void convert_x_kernel(const float* __restrict__ x1, const float* __restrict__ x2) {
    int blk = blockIdx.x;
    int t = blk >> 12, bi = blk & 4095;
    const float* x = (t ? x2 : x1) + (size_t)bi * D_;
    __half* xh = (t ? g_x2h : g_x1h) + (size_t)bi * D_;
    __half* xl = (t ? g_x2l : g_x1l) + (size_t)bi * D_;
    int tid = threadIdx.x;
    float ss = 0.0f;
    #pragma unroll
    for (int j = 0; j < 4; ++j) {
        int p = (tid + j * 256) * 4;
        float4 v = *reinterpret_cast<const float4*>(x + p);
        ss += v.x * v.x + v.y * v.y + v.z * v.z + v.w * v.w;
        uint2 h, lo;
        split4h(v, h, lo);
        *reinterpret_cast<uint2*>(xh + p) = h;
        *reinterpret_cast<uint2*>(xl + p) = lo;
    }
    ss = block_sum(ss);
    if (tid == 0) (t ? g_n2 : g_n1)[bi] = sqrtf(ss);
}

__global__ void convert_w_kernel(const float* __restrict__ Wx, const float* __restrict__ Wn,
                                 const float* __restrict__ Wr) {
    int i = blockIdx.x * 256 + threadIdx.x;          // < 786432
    int seg = i >> 18, off = i & 262143;
    float v = (seg == 0 ? Wx : seg == 1 ? Wn : Wr)[off];
    g_Wh[i] = __float2half(v);
}

__global__ void transpose_kernel(const float* __restrict__ x1, const float* __restrict__ x2) {
    __shared__ float t[32][33];
    int which = blockIdx.z >> 3, b = blockIdx.z & 7;
    const float* x = (which ? x2 : x1) + (size_t)b * S_ * D_;
    __half* xth = (which ? g_x2th : g_x1th) + (size_t)b * D_ * S_;
    int d0 = blockIdx.x * 32, i0 = blockIdx.y * 32;
    int tx = threadIdx.x, ty = threadIdx.y;
    #pragma unroll
    for (int k = 0; k < 32; k += 8)
        t[ty + k][tx] = x[(size_t)(i0 + ty + k) * D_ + d0 + tx];
    __syncthreads();
    #pragma unroll
    for (int k = 0; k < 32; k += 8) {
        size_t o = (size_t)(d0 + ty + k) * S_ + i0 + tx;
        xth[o] = __float2half(t[tx][ty + k]);
    }
}

__global__ void neigh_idx_kernel(const int* __restrict__ adj1, const int* __restrict__ adj2) {
    int row = blockIdx.x * 8 + (threadIdx.x >> 5);
    int lane = threadIdx.x & 31;
    int t = row >> 12, bi = row & 4095;
    int b = bi >> 9, i = bi & 511;
    const int* arow = (t ? adj2 : adj1) + ((size_t)b * S_ + i) * S_;
    int* lst = g_nidx + (size_t)row * 512;
    int cnt = 0;
    for (int jj = lane; jj < S_; jj += 32) {
        bool f = (arow[jj] > 0) && (jj != i);
        unsigned m = __ballot_sync(0xffffffffu, f);
        if (f) lst[cnt + __popc(m & ((1u << lane) - 1))] = jj;
        cnt += __popc(m);
    }
    if (lane == 0) g_ndeg[row] = cnt;
}

__global__ void neigh_gather_kernel(const float* __restrict__ x1, const float* __restrict__ x2) {
    int blk = blockIdx.x;
    int t = blk >> 12, bi = blk & 4095;
    int b = bi >> 9;
    const float* x = (t ? x2 : x1) + (size_t)b * S_ * D_;
    __half* nh = (t ? g_nb2h : g_nb1h) + (size_t)bi * D_;
    __half* nl = (t ? g_nb2l : g_nb1l) + (size_t)bi * D_;
    int tid = threadIdx.x;
    __shared__ int sidx[512];
    __shared__ int sdeg;
    if (tid == 0) sdeg = g_ndeg[blk];
    __syncthreads();
    int deg = sdeg;
    for (int k = tid; k < deg; k += 256) sidx[k] = g_nidx[(size_t)blk * 512 + k];
    __syncthreads();
    float4 acc[4];
    #pragma unroll
    for (int j = 0; j < 4; ++j) acc[j] = make_float4(0.f, 0.f, 0.f, 0.f);
    for (int k = 0; k < deg; ++k) {
        const float* xr = x + (size_t)sidx[k] * D_;
        #pragma unroll
        for (int j = 0; j < 4; ++j) {
            float4 v = *reinterpret_cast<const float4*>(xr + (tid + j * 256) * 4);
            acc[j].x += v.x; acc[j].y += v.y; acc[j].z += v.z; acc[j].w += v.w;
        }
    }
    float inv = 1.0f / (float)deg;
    #pragma unroll
    for (int j = 0; j < 4; ++j) {
        int p = (tid + j * 256) * 4;
        float4 v = make_float4(acc[j].x * inv, acc[j].y * inv, acc[j].z * inv, acc[j].w * inv);
        uint2 h, lo;
        split4h(v, h, lo);
        *reinterpret_cast<uint2*>(nh + p) = h;
        *reinterpret_cast<uint2*>(nl + p) = lo;
    }
}

__global__ void softmax_row_kernel() {
    int bi = blockIdx.x;
    const float* srow = g_sim + (size_t)bi * S_;
    __half* dh = g_a1h + (size_t)bi * S_;
    __half* dl = g_a1l + (size_t)bi * S_;
    int tid = threadIdx.x;
    float v0 = srow[tid], v1 = srow[tid + 256];
    float mx = block_max(fmaxf(v0, v1));
    float e0 = expf(v0 - mx), e1 = expf(v1 - mx);
    float s = block_sum(e0 + e1);
    float inv = 1.0f / s;
    float a0 = e0 * inv, a1 = e1 * inv;
    __half h0 = __float2half(a0), h1 = __float2half(a1);
    dh[tid] = h0;        dl[tid] = __float2half(a0 - __half2float(h0));
    dh[tid + 256] = h1;  dl[tid + 256] = __float2half(a1 - __half2float(h1));
}

__global__ void softmax_col_kernel() {
    int bi = blockIdx.x;
    int b = bi >> 9, j = bi & 511;
    const float* base = g_sim + (size_t)b * S_ * S_ + j;
    __half* dh = g_a2h + (size_t)bi * S_;
    __half* dl = g_a2l + (size_t)bi * S_;
    int tid = threadIdx.x;
    float v0 = base[(size_t)tid * S_];
    float v1 = base[(size_t)(tid + 256) * S_];
    float mx = block_max(fmaxf(v0, v1));
    float e0 = expf(v0 - mx), e1 = expf(v1 - mx);
    float s = block_sum(e0 + e1);
    float inv = 1.0f / s;
    float a0 = e0 * inv, a1 = e1 * inv;
    __half h0 = __float2half(a0), h1 = __float2half(a1);
    dh[tid] = h0;        dl[tid] = __float2half(a0 - __half2float(h0));
    dh[tid + 256] = h1;  dl[tid + 256] = __float2half(a1 - __half2float(h1));
}

__global__ void normrelu_stats_kernel(const float* __restrict__ out) {
    size_t row0 = (size_t)blockIdx.x * 16;
    int stream = (row0 >= (size_t)MROWS) ? 1 : 0;
    int tid = threadIdx.x;
    float s[6] = {}, q[6] = {};
    for (int rr = 0; rr < 16; ++rr) {
        const float* p = out + (row0 + rr) * (size_t)C_;
        float v[6];
        float ss = 0.0f;
        #pragma unroll
        for (int k = 0; k < 6; k++) { v[k] = p[tid + k * 256]; ss += v[k] * v[k]; }
        ss = block_sum(ss);
        float inv = 1.0f / fmaxf(sqrtf(ss), 1e-12f);
        if (tid == 0) g_rinv[row0 + rr] = inv;
        #pragma unroll
        for (int k = 0; k < 6; k++) {
            float y = fmaxf(v[k] * inv, 0.0f);
            s[k] += y; q[k] += y * y;
        }
        __syncthreads();
    }
    #pragma unroll
    for (int k = 0; k < 6; k++) {
        atomicAdd(&g_sums [stream * C_ + tid + k * 256], s[k]);
        atomicAdd(&g_sumsq[stream * C_ + tid + k * 256], q[k]);
    }
}

__global__ void bn_finalize_kernel(const float* __restrict__ gamma,
                                   const float* __restrict__ beta) {
    int i = blockIdx.x * 256 + threadIdx.x;
    if (i < 2 * C_) {
        int c = (i >= C_) ? (i - C_) : i;
        float m = g_sums[i] * (1.0f / MROWS);
        float var = g_sumsq[i] * (1.0f / MROWS) - m * m;
        float sc = gamma[c] * rsqrtf(var + 1e-5f);
        g_scalev[i] = sc;
        g_shiftv[i] = beta[c] - m * sc;
    }
}

__global__ void bn_apply_kernel(float* __restrict__ out) {
    size_t row = blockIdx.x;
    int stream = (row >= (size_t)MROWS) ? 1 : 0;
    float rinv = g_rinv[row];
    float4* p = reinterpret_cast<float4*>(out + row * (size_t)C_);
    const float4* sc = reinterpret_cast<const float4*>(g_scalev + stream * C_);
    const float4* sh = reinterpret_cast<const float4*>(g_shiftv + stream * C_);
    int tid = threadIdx.x;          // 0..383
    float4 h = p[tid], s4 = sc[tid], b4 = sh[tid];
    float4 o;
    o.x = fmaxf(h.x * rinv, 0.0f) * s4.x + b4.x;
    o.y = fmaxf(h.y * rinv, 0.0f) * s4.y + b4.y;
    o.z = fmaxf(h.z * rinv, 0.0f) * s4.z + b4.z;
    o.w = fmaxf(h.w * rinv, 0.0f) * s4.w + b4.w;
    p[tid] = o;
}

// ---------------- launch ----------------
extern "C" void kernel_launch(void* const* d_in, const int* in_sizes, int n_in,
                              void* d_out, int out_size) {
    const float* x1    = (const float*)d_in[0];
    const float* x2    = (const float*)d_in[1];
    const int*   adj1  = (const int*)  d_in[2];
    const int*   adj2  = (const int*)  d_in[3];
    const float* Wx    = (const float*)d_in[4];
    const float* bx    = (const float*)d_in[5];
    const float* Wn    = (const float*)d_in[6];
    const float* bnn   = (const float*)d_in[7];
    const float* Wr    = (const float*)d_in[8];
    const float* br    = (const float*)d_in[9];
    const float* gamma = (const float*)d_in[10];
    const float* beta  = (const float*)d_in[11];
    float* out = (float*)d_out;

    static cudaStream_t s1 = []() {
        cudaStream_t s; cudaStreamCreateWithFlags(&s, cudaStreamNonBlocking); return s;
    }();
    static cudaEvent_t ev_root = []() {
        cudaEvent_t e; cudaEventCreateWithFlags(&e, cudaEventDisableTiming); return e;
    }();
    static cudaEvent_t ev_tr = []() {
        cudaEvent_t e; cudaEventCreateWithFlags(&e, cudaEventDisableTiming); return e;
    }();
    static cudaEvent_t ev_side = []() {
        cudaEvent_t e; cudaEventCreateWithFlags(&e, cudaEventDisableTiming); return e;
    }();
    static cudaEvent_t ev_cx = []() {
        cudaEvent_t e; cudaEventCreateWithFlags(&e, cudaEventDisableTiming); return e;
    }();
    static cudaEvent_t ev_linxn = []() {
        cudaEvent_t e; cudaEventCreateWithFlags(&e, cudaEventDisableTiming); return e;
    }();

    cudaFuncSetAttribute(sim_mma_kernel, cudaFuncAttributeMaxDynamicSharedMemorySize, SMEM_BYTES);
    cudaFuncSetAttribute(mu_mma_kernel,  cudaFuncAttributeMaxDynamicSharedMemorySize, SMEM_BYTES);
    cudaFuncSetAttribute(lin_mma_kernel, cudaFuncAttributeMaxDynamicSharedMemorySize, SMEM_BYTES);

    // fork side stream
    cudaEventRecord(ev_root, 0);
    cudaStreamWaitEvent(s1, ev_root, 0);

    // side chain
    zero_stats_kernel<<<12, 256, 0, s1>>>();
    transpose_kernel<<<dim3(128, 16, 16), dim3(32, 8), 0, s1>>>(x1, x2);
    cudaEventRecord(ev_tr, s1);
    neigh_idx_kernel<<<1024, 256, 0, s1>>>(adj1, adj2);
    neigh_gather_kernel<<<8192, 256, 0, s1>>>(x1, x2);
    convert_w_kernel<<<3072, 256, 0, s1>>>(Wx, Wn, Wr);
    cudaEventRecord(ev_side, s1);

    // main chain head
    convert_x_kernel<<<8192, 256>>>(x1, x2);
    cudaEventRecord(ev_cx, 0);

    // side: lin over x/nb segments (no mu dependency), overlaps sim/softmax/mu
    cudaStreamWaitEvent(s1, ev_cx, 0);
    lin_mma_kernel<<<dim3(4, 256, 4), 256, SMEM_BYTES, s1>>>(bx, bnn, br, out, 0);
    cudaEventRecord(ev_linxn, s1);

    // main chain
    sim_mma_kernel<<<dim3(4, 4, 8), 256, SMEM_BYTES>>>();
    softmax_row_kernel<<<4096, 256>>>();
    softmax_col_kernel<<<4096, 256>>>();
    cudaStreamWaitEvent(0, ev_tr, 0);
    mu_mma_kernel<<<dim3(32, 4, 8), 256, SMEM_BYTES>>>(x1, x2, 0);
    mu_mma_kernel<<<dim3(32, 4, 8), 256, SMEM_BYTES>>>(x1, x2, 1);
    cudaStreamWaitEvent(0, ev_side, 0);
    lin_mma_kernel<<<dim3(4, 256, 2), 256, SMEM_BYTES>>>(bx, bnn, br, out, 1);
    cudaStreamWaitEvent(0, ev_linxn, 0);
    normrelu_stats_kernel<<<4096, 256>>>(out);
    bn_finalize_kernel<<<12, 256>>>(gamma, beta);
    bn_apply_kernel<<<65536, 384>>>(out);
}